// round 12
// baseline (speedup 1.0000x reference)
#include <cuda_runtime.h>
#include <math.h>

#define Bn 4
#define CIN 128
#define Np 4096
#define Hd 128
#define COUT 256
#define Kn 16
#define SEH 64
#define NCHUNK 16
#define EPSB 1e-5f
#define NT 32   // 4096/128 tiles
#define TSTRIDE 132
#define WCAP 256

typedef unsigned long long u64;

// ---------------- scratch (static __device__, no allocations) ----------------
__device__ float g_sq[Bn * Np];
__device__ float g_d2[(size_t)Bn * Np * Np];        // 256 MiB
__device__ float g_rmin[(size_t)Bn * Np * NT];      // per-(row, tile) minima, 2 MiB
__device__ int   g_idx[Bn * Np * Kn];
__device__ float g_W1T[CIN * Hd];                   // [c][h]
__device__ float g_WCT[CIN * Hd];                   // [c][h]
__device__ float g_beff[Hd];
__device__ float g_WfuseT[Hd * COUT];               // [h][o]
__device__ float g_b2[COUT];
__device__ float g_WresT[CIN * COUT];               // [c][o]
__device__ float g_b3[COUT];
__device__ float g_A[(size_t)Bn * Np * Hd];
__device__ float g_C[(size_t)Bn * Np * Hd];
__device__ float g_outpre[(size_t)Bn * Np * COUT];
__device__ float g_separt[Bn * NCHUNK * 8 * COUT];
__device__ float g_se[Bn * NCHUNK * COUT];

__device__ __forceinline__ u64 ffma2(u64 a, u64 b, u64 c) {
    u64 d;
    asm("fma.rn.f32x2 %0, %1, %2, %3;" : "=l"(d) : "l"(a), "l"(b), "l"(c));
    return d;
}
union F2U { u64 u; float2 f; };

__device__ __forceinline__ u64 mk_key(float f, unsigned idx) {
    unsigned u = __float_as_uint(f);
    unsigned ord = (f < 0.f) ? ~u : (u | 0x80000000u);
    return ((u64)ord << 32) | idx;
}

__device__ __forceinline__ unsigned f2tf32(float v) {
    unsigned r;
    asm("cvt.rna.tf32.f32 %0, %1;" : "=r"(r) : "f"(v));
    return r;
}

__device__ __forceinline__ void mma_tf32(float* d, const unsigned* a,
                                         unsigned b0, unsigned b1) {
    asm volatile(
        "mma.sync.aligned.m16n8k8.row.col.f32.tf32.tf32.f32 "
        "{%0,%1,%2,%3}, {%4,%5,%6,%7}, {%8,%9}, {%0,%1,%2,%3};"
        : "+f"(d[0]), "+f"(d[1]), "+f"(d[2]), "+f"(d[3])
        : "r"(a[0]), "r"(a[1]), "r"(a[2]), "r"(a[3]), "r"(b0), "r"(b1));
}

// ---------------- prep: fold all BN into weights ----------------
__global__ void prep_kernel(const float* __restrict__ W_edge,
                            const float* __restrict__ g1, const float* __restrict__ b1,
                            const float* __restrict__ m1, const float* __restrict__ v1,
                            const float* __restrict__ W_fuse,
                            const float* __restrict__ g2, const float* __restrict__ b2,
                            const float* __restrict__ m2, const float* __restrict__ v2,
                            const float* __restrict__ W_res,
                            const float* __restrict__ g3, const float* __restrict__ b3,
                            const float* __restrict__ m3, const float* __restrict__ v3) {
    int i = blockIdx.x * blockDim.x + threadIdx.x;
    int stride = gridDim.x * blockDim.x;
    for (int t = i; t < CIN * Hd; t += stride) {
        int h = t % Hd, c = t / Hd;
        float s = g1[h] * rsqrtf(v1[h] + EPSB);
        float w1 = W_edge[h * (2 * CIN) + c];
        float w2 = W_edge[h * (2 * CIN) + CIN + c];
        g_W1T[t] = w1 * s;
        g_WCT[t] = (w2 - w1) * s;
    }
    for (int h = i; h < Hd; h += stride) {
        float s = g1[h] * rsqrtf(v1[h] + EPSB);
        g_beff[h] = b1[h] - m1[h] * s;
    }
    for (int t = i; t < Hd * COUT; t += stride) {
        int o = t % COUT, h = t / COUT;
        float s = g2[o] * rsqrtf(v2[o] + EPSB);
        g_WfuseT[t] = W_fuse[o * Hd + h] * s;
    }
    for (int o = i; o < COUT; o += stride) {
        float s2 = g2[o] * rsqrtf(v2[o] + EPSB);
        g_b2[o] = b2[o] - m2[o] * s2;
        float s3 = g3[o] * rsqrtf(v3[o] + EPSB);
        g_b3[o] = b3[o] - m3[o] * s3;
    }
    for (int t = i; t < CIN * COUT; t += stride) {
        int o = t % COUT, c = t / COUT;
        float s3 = g3[o] * rsqrtf(v3[o] + EPSB);
        g_WresT[t] = W_res[o * CIN + c] * s3;
    }
}

// ---------------- squared norms ----------------
__global__ void sq_kernel(const float* __restrict__ x) {
    int b = blockIdx.y;
    int n = blockIdx.x * 256 + threadIdx.x;
    const float* xb = x + (size_t)b * CIN * Np;
    float s = 0.f;
    for (int c = 0; c < CIN; c++) {
        float v = xb[(size_t)c * Np + n];
        s = fmaf(v, v, s);
    }
    g_sq[b * Np + n] = s;
}

// ---------------- symmetric d2 via 3xTF32 tensor-core GEMM ----------------
// dot = hi*hi' + hi*lo' + lo*hi' with hi = tf32(x), lo = tf32(x - hi).
// Dropped lo*lo' term is <= 2^-22 relative: same magnitude as fp32 rounding.
// Epilogue (stage -> store + rmin + mirror + colmin) identical structure.
extern __shared__ float s_dyn[];

__global__ __launch_bounds__(256, 2) void d2_kernel(const float* __restrict__ x) {
    int b = blockIdx.y;
    int ti = 0, rem = blockIdx.x;
    while (rem >= NT - ti) { rem -= NT - ti; ti++; }
    int tj = ti + rem;
    int i0 = ti * 128, j0 = tj * 128;

    float* s_tile = s_dyn;                    // 128 x TSTRIDE (epilogue only)
    float* sAh = s_dyn;                       // mainloop planes (overlay)
    float* sAl = s_dyn + 8 * TSTRIDE;
    float* sBh = s_dyn + 16 * TSTRIDE;
    float* sBl = s_dyn + 24 * TSTRIDE;
    __shared__ float s_sqi[128], s_sqj[128];
    __shared__ float colmin[128];

    int tid = threadIdx.x;
    int lane = tid & 31, w = tid >> 5;
    if (tid < 128) s_sqi[tid] = g_sq[b * Np + i0 + tid];
    else           s_sqj[tid - 128] = g_sq[b * Np + j0 + tid - 128];

    const float* xb = x + (size_t)b * CIN * Np;

    float acc[2][8][4];
#pragma unroll
    for (int s = 0; s < 2; s++)
#pragma unroll
        for (int j = 0; j < 8; j++)
#pragma unroll
            for (int q = 0; q < 4; q++) acc[s][j][q] = 0.f;

    int m0w = (w >> 1) * 32;      // warp row offset
    int n0w = (w & 1) * 64;       // warp col offset
    int ar = lane >> 2, ak = lane & 3;
    int loadk = tid >> 5, loadi = (tid & 31) * 4;

    for (int c0 = 0; c0 < CIN; c0 += 8) {
        __syncthreads();
        const float* rowp = xb + (size_t)(c0 + loadk) * Np;
        float4 va = *(const float4*)(rowp + i0 + loadi);
        float4 vb = *(const float4*)(rowp + j0 + loadi);
        float av[4] = {va.x, va.y, va.z, va.w};
        float bv[4] = {vb.x, vb.y, vb.z, vb.w};
        float ah[4], al[4], bh[4], bl[4];
#pragma unroll
        for (int q = 0; q < 4; q++) {
            float h = __uint_as_float(f2tf32(av[q]));
            ah[q] = h;
            al[q] = __uint_as_float(f2tf32(av[q] - h));
            h = __uint_as_float(f2tf32(bv[q]));
            bh[q] = h;
            bl[q] = __uint_as_float(f2tf32(bv[q] - h));
        }
        int sb = loadk * TSTRIDE + loadi;
        *(float4*)&sAh[sb] = make_float4(ah[0], ah[1], ah[2], ah[3]);
        *(float4*)&sAl[sb] = make_float4(al[0], al[1], al[2], al[3]);
        *(float4*)&sBh[sb] = make_float4(bh[0], bh[1], bh[2], bh[3]);
        *(float4*)&sBl[sb] = make_float4(bl[0], bl[1], bl[2], bl[3]);
        __syncthreads();

        unsigned a_h[2][4], a_l[2][4];
#pragma unroll
        for (int s = 0; s < 2; s++) {
            int rb = m0w + 16 * s + ar;
            a_h[s][0] = __float_as_uint(sAh[ak * TSTRIDE + rb]);
            a_h[s][1] = __float_as_uint(sAh[ak * TSTRIDE + rb + 8]);
            a_h[s][2] = __float_as_uint(sAh[(ak + 4) * TSTRIDE + rb]);
            a_h[s][3] = __float_as_uint(sAh[(ak + 4) * TSTRIDE + rb + 8]);
            a_l[s][0] = __float_as_uint(sAl[ak * TSTRIDE + rb]);
            a_l[s][1] = __float_as_uint(sAl[ak * TSTRIDE + rb + 8]);
            a_l[s][2] = __float_as_uint(sAl[(ak + 4) * TSTRIDE + rb]);
            a_l[s][3] = __float_as_uint(sAl[(ak + 4) * TSTRIDE + rb + 8]);
        }
#pragma unroll
        for (int j = 0; j < 8; j++) {
            int nb = n0w + 8 * j + ar;
            unsigned bh0 = __float_as_uint(sBh[ak * TSTRIDE + nb]);
            unsigned bh1 = __float_as_uint(sBh[(ak + 4) * TSTRIDE + nb]);
            unsigned bl0 = __float_as_uint(sBl[ak * TSTRIDE + nb]);
            unsigned bl1 = __float_as_uint(sBl[(ak + 4) * TSTRIDE + nb]);
#pragma unroll
            for (int s = 0; s < 2; s++) {
                mma_tf32(acc[s][j], a_h[s], bh0, bh1);
                mma_tf32(acc[s][j], a_h[s], bl0, bl1);
                mma_tf32(acc[s][j], a_l[s], bh0, bh1);
            }
        }
    }
    __syncthreads();   // planes dead; s_tile staging begins

    // stage d2 = sq_i + sq_j - 2*dot into s_tile
#pragma unroll
    for (int s = 0; s < 2; s++) {
        int r = m0w + 16 * s + ar;
        float sq0 = s_sqi[r], sq1 = s_sqi[r + 8];
#pragma unroll
        for (int j = 0; j < 8; j++) {
            int c = n0w + 8 * j + 2 * ak;
            float sj0 = s_sqj[c], sj1 = s_sqj[c + 1];
            *(float2*)&s_tile[r * TSTRIDE + c] =
                make_float2(sq0 + sj0 - 2.f * acc[s][j][0],
                            sq0 + sj1 - 2.f * acc[s][j][1]);
            *(float2*)&s_tile[(r + 8) * TSTRIDE + c] =
                make_float2(sq1 + sj0 - 2.f * acc[s][j][2],
                            sq1 + sj1 - 2.f * acc[s][j][3]);
        }
    }
    __syncthreads();

    float* d2b = g_d2 + (size_t)b * Np * Np;
    // direct store (coalesced float4) + fused row minima
    {
        int r = tid >> 1, h = tid & 1;
        const float4* src = (const float4*)(s_tile + r * TSTRIDE + h * 64);
        float4* dst = (float4*)(d2b + (size_t)(i0 + r) * Np + j0 + h * 64);
        float rm = INFINITY;
#pragma unroll
        for (int q = 0; q < 16; q++) {
            float4 v = src[q];
            dst[q] = v;
            rm = fminf(rm, fminf(fminf(v.x, v.y), fminf(v.z, v.w)));
        }
        float o = __shfl_xor_sync(0xffffffffu, rm, 1);
        rm = fminf(rm, o);
        if (h == 0) g_rmin[((size_t)(b * Np + i0 + r)) * NT + tj] = rm;
    }
    if (ti != tj) {
        // transposed store (coalesced over il)
        for (int idx = tid; idx < 128 * 128; idx += 256) {
            int jl = idx >> 7, il = idx & 127;
            d2b[(size_t)(j0 + jl) * Np + i0 + il] = s_tile[il * TSTRIDE + jl];
        }
        // column minima -> row minima of the mirrored rows (2 threads/col)
        {
            int col = tid & 127, half = tid >> 7;
            float cm = INFINITY;
            int il0 = half * 64;
            for (int il = il0; il < il0 + 64; il++)
                cm = fminf(cm, s_tile[il * TSTRIDE + col]);
            if (half == 0) colmin[col] = cm;
            __syncthreads();
            if (half == 1)
                g_rmin[((size_t)(b * Np + j0 + col)) * NT + ti] = fminf(cm, colmin[col]);
        }
    }
}

// ---------------- top-16: warp-per-row, tile-min threshold + tile skipping ----
__global__ __launch_bounds__(256, 8) void topk_kernel() {
    int tid = threadIdx.x;
    int lane = tid & 31, w = tid >> 5;
    int b = blockIdx.y;
    int n = blockIdx.x * 8 + w;
    const float* row = g_d2 + ((size_t)b * Np + n) * Np;

    __shared__ u64 wcand[8][WCAP];   // 16 KB, per-warp segments

    float rm = g_rmin[((size_t)(b * Np + n)) * NT + lane];
    {
        float v = rm;
#pragma unroll
        for (int k = 2; k <= 32; k <<= 1) {
#pragma unroll
            for (int j = k >> 1; j > 0; j >>= 1) {
                float o = __shfl_xor_sync(0xffffffffu, v, j);
                bool dirDesc = (lane & k) != 0;
                bool lower = (lane & j) == 0;
                bool takeMin = (lower != dirDesc);
                v = takeMin ? fminf(v, o) : fmaxf(v, o);
            }
        }
        float Tf_ = __shfl_sync(0xffffffffu, v, 15);
        unsigned tmask = __ballot_sync(0xffffffffu, rm <= Tf_);
        int cnt = 0;
        bool over = false;
        unsigned m = tmask;
        while (m) {
            int t = __ffs(m) - 1;
            m &= m - 1;
            float4 vv = *(const float4*)(row + t * 128 + lane * 4);
            float fv[4] = {vv.x, vv.y, vv.z, vv.w};
#pragma unroll
            for (int q = 0; q < 4; q++) {
                bool p = fv[q] <= Tf_;
                unsigned bm = __ballot_sync(0xffffffffu, p);
                if (p) {
                    int pos = cnt + __popc(bm & ((1u << lane) - 1u));
                    if (pos < WCAP) wcand[w][pos] = mk_key(fv[q], t * 128 + lane * 4 + q);
                    else over = true;
                }
                cnt += __popc(bm);
            }
        }
        over = __any_sync(0xffffffffu, over) || (cnt > WCAP);
        __syncwarp();

        int* outp = g_idx + ((b * Np + n) * Kn);
        if (!over) {
            for (int it = 0; it < Kn; it++) {
                u64 best = ~0ull; int bslot = -1;
                for (int s = lane; s < cnt; s += 32) {
                    u64 kk = wcand[w][s];
                    if (kk < best) { best = kk; bslot = s; }
                }
                u64 k = best;
#pragma unroll
                for (int off = 16; off; off >>= 1) {
                    u64 o = __shfl_xor_sync(0xffffffffu, k, off);
                    if (o < k) k = o;
                }
                if (lane == 0) outp[it] = (int)(unsigned)(k & 0xffffffffull);
                if (best == k && bslot >= 0) wcand[w][bslot] = ~0ull;
                __syncwarp();
            }
        } else {
            u64 last = 0;
            for (int it = 0; it < Kn; it++) {
                u64 best = ~0ull;
                for (int s = lane; s < Np; s += 32) {
                    u64 kk = mk_key(row[s], s);
                    if (kk > last && kk < best) best = kk;
                }
                u64 k = best;
#pragma unroll
                for (int off = 16; off; off >>= 1) {
                    u64 o = __shfl_xor_sync(0xffffffffu, k, off);
                    if (o < k) k = o;
                }
                if (lane == 0) outp[it] = (int)(unsigned)(k & 0xffffffffull);
                last = k;
            }
        }
    }
}

// ---------------- A/C projection GEMMs (FFMA2) ----------------
__global__ __launch_bounds__(256, 2) void ac_gemm(const float* __restrict__ x) {
    int b = blockIdx.y;
    int n0 = blockIdx.x * 128;
    int which = blockIdx.z;
    const float* WT = which ? g_WCT : g_W1T;
    const float* xb = x + (size_t)b * CIN * Np;
    __shared__ __align__(16) float As2[8][256];
    __shared__ __align__(16) float Bs[8][128];
    u64 acc2[8][4];
#pragma unroll
    for (int a = 0; a < 8; a++)
#pragma unroll
        for (int c = 0; c < 4; c++) acc2[a][c] = 0ull;
    int tid = threadIdx.x;
    int lx = tid & 15, ly = tid >> 4;
    int loadc = tid >> 5, loadi = (tid & 31) * 4;
    for (int c0 = 0; c0 < CIN; c0 += 8) {
        float4 va = *(const float4*)(xb + (size_t)(c0 + loadc) * Np + n0 + loadi);
        *(float4*)&As2[loadc][2 * loadi]     = make_float4(va.x, va.x, va.y, va.y);
        *(float4*)&As2[loadc][2 * loadi + 4] = make_float4(va.z, va.z, va.w, va.w);
        *(float4*)&Bs[loadc][loadi] = *(const float4*)(WT + (size_t)(c0 + loadc) * Hd + loadi);
        __syncthreads();
#pragma unroll
        for (int k = 0; k < 8; k++) {
            u64 ar2[8], br2[4];
#pragma unroll
            for (int a = 0; a < 8; a++) ar2[a] = *(const u64*)&As2[k][2 * (ly + 16 * a)];
#pragma unroll
            for (int c = 0; c < 4; c++) br2[c] = *(const u64*)&Bs[k][2 * lx + 32 * c];
#pragma unroll
            for (int a = 0; a < 8; a++)
#pragma unroll
                for (int c = 0; c < 4; c++) acc2[a][c] = ffma2(ar2[a], br2[c], acc2[a][c]);
        }
        __syncthreads();
    }
    float* outb = which ? g_C : g_A;
#pragma unroll
    for (int a = 0; a < 8; a++) {
        int n = n0 + ly + 16 * a;
#pragma unroll
        for (int c = 0; c < 4; c++) {
            int h = 2 * lx + 32 * c;
            F2U cv; cv.u = acc2[a][c];
            float v0 = cv.f.x, v1 = cv.f.y;
            if (which) {
                float2 be = *(const float2*)&g_beff[h];
                v0 += be.x; v1 += be.y;
            }
            *(float2*)&outb[((size_t)b * Np + n) * Hd + h] = make_float2(v0, v1);
        }
    }
}

// ---------------- attention + aggregate + fuse (per query) ----------------
__global__ __launch_bounds__(128) void attn_kernel(const float* __restrict__ w_att) {
    int b = blockIdx.y, n = blockIdx.x;
    int tid = threadIdx.x;
    __shared__ float shp[4][Kn];
    __shared__ float tk[Kn];
    __shared__ float aggs[Hd];
    const int* id = g_idx + ((b * Np + n) * Kn);
    const float* Ab = g_A + (size_t)b * Np * Hd;
    float Cc = g_C[((size_t)b * Np + n) * Hd + tid];
    float hk[Kn];
#pragma unroll
    for (int k = 0; k < Kn; k++) {
        int j = id[k];
        hk[k] = fmaxf(Ab[(size_t)j * Hd + tid] + Cc, 0.f);
    }
    float wa = w_att[tid];
    int lane = tid & 31, w = tid >> 5;
#pragma unroll
    for (int k = 0; k < Kn; k++) {
        float p = hk[k] * wa;
#pragma unroll
        for (int off = 16; off > 0; off >>= 1) p += __shfl_down_sync(0xffffffffu, p, off);
        if (lane == 0) shp[w][k] = p;
    }
    __syncthreads();
    if (tid < Kn) tk[tid] = shp[0][tid] + shp[1][tid] + shp[2][tid] + shp[3][tid];
    __syncthreads();
    float mx = -INFINITY;
#pragma unroll
    for (int k = 0; k < Kn; k++) mx = fmaxf(mx, tk[k]);
    float e[Kn]; float ssum = 0.f;
#pragma unroll
    for (int k = 0; k < Kn; k++) { e[k] = __expf(tk[k] - mx); ssum += e[k]; }
    float inv = 1.f / ssum;
    float agg = 0.f;
#pragma unroll
    for (int k = 0; k < Kn; k++) agg = fmaf(e[k], hk[k], agg);
    agg *= inv;
    aggs[tid] = agg;
    __syncthreads();
    float o0 = g_b2[tid], o1 = g_b2[tid + 128];
#pragma unroll 8
    for (int h = 0; h < Hd; h++) {
        float av = aggs[h];
        o0 = fmaf(av, g_WfuseT[h * COUT + tid], o0);
        o1 = fmaf(av, g_WfuseT[h * COUT + tid + 128], o1);
    }
    float* op = g_outpre + ((size_t)b * Np + n) * COUT;
    op[tid]       = fmaxf(o0, 0.f);
    op[tid + 128] = fmaxf(o1, 0.f);
}

// ---------------- SE stage 1: partial sums (512 blocks) ----------------
__global__ __launch_bounds__(256) void se_sum_kernel() {
    int b = blockIdx.y, ch = blockIdx.x, z = blockIdx.z;
    int tid = threadIdx.x;
    const float* op = g_outpre + ((size_t)b * Np + (size_t)ch * 256 + (size_t)z * 32) * COUT;
    float s = 0.f;
#pragma unroll 8
    for (int q = 0; q < 32; q++) s += op[(size_t)q * COUT + tid];
    g_separt[(((b * NCHUNK) + ch) * 8 + z) * COUT + tid] = s;
}

// ---------------- SE stage 2: combine + MLP ----------------
__global__ __launch_bounds__(256) void se_mlp_kernel(const float* __restrict__ fc1_w,
                                                     const float* __restrict__ fc1_b,
                                                     const float* __restrict__ fc2_w,
                                                     const float* __restrict__ fc2_b) {
    int b = blockIdx.y, ch = blockIdx.x;
    int tid = threadIdx.x;
    float s = 0.f;
#pragma unroll
    for (int z = 0; z < 8; z++)
        s += g_separt[(((b * NCHUNK) + ch) * 8 + z) * COUT + tid];
    __shared__ float mean[COUT];
    __shared__ float u[SEH];
    mean[tid] = s * (1.f / 256.f);
    __syncthreads();
    if (tid < SEH) {
        float acc = fc1_b[tid];
        for (int c = 0; c < COUT; c++) acc = fmaf(mean[c], fc1_w[tid * COUT + c], acc);
        u[tid] = fmaxf(acc, 0.f);
    }
    __syncthreads();
    float acc = fc2_b[tid];
#pragma unroll
    for (int j = 0; j < SEH; j++) acc = fmaf(u[j], fc2_w[tid * SEH + j], acc);
    g_se[(b * NCHUNK + ch) * COUT + tid] = 1.f / (1.f + __expf(-acc));
}

// ---------------- residual GEMM (FFMA2) + SE-scale + combine ----------------
__global__ __launch_bounds__(256, 2) void final_kernel(const float* __restrict__ x,
                                                       float* __restrict__ out) {
    int b = blockIdx.z;
    int n0 = blockIdx.x * 128;
    int o0 = blockIdx.y * 128;
    const float* xb = x + (size_t)b * CIN * Np;
    __shared__ __align__(16) float As[8][128];
    __shared__ __align__(16) float Bs2[8][256];
    u64 acc2[4][8];
#pragma unroll
    for (int a = 0; a < 4; a++)
#pragma unroll
        for (int c = 0; c < 8; c++) acc2[a][c] = 0ull;
    int tid = threadIdx.x;
    int lx = tid & 15, ly = tid >> 4;
    int loadc = tid >> 5, loadi = (tid & 31) * 4;
    for (int c0 = 0; c0 < CIN; c0 += 8) {
        *(float4*)&As[loadc][loadi] = *(const float4*)(xb + (size_t)(c0 + loadc) * Np + n0 + loadi);
        float4 vb = *(const float4*)(g_WresT + (size_t)(c0 + loadc) * COUT + o0 + loadi);
        *(float4*)&Bs2[loadc][2 * loadi]     = make_float4(vb.x, vb.x, vb.y, vb.y);
        *(float4*)&Bs2[loadc][2 * loadi + 4] = make_float4(vb.z, vb.z, vb.w, vb.w);
        __syncthreads();
#pragma unroll
        for (int k = 0; k < 8; k++) {
            u64 ar2[4], br2[8];
#pragma unroll
            for (int a = 0; a < 4; a++) ar2[a] = *(const u64*)&As[k][2 * lx + 32 * a];
#pragma unroll
            for (int c = 0; c < 8; c++) br2[c] = *(const u64*)&Bs2[k][2 * (ly + 16 * c)];
#pragma unroll
            for (int a = 0; a < 4; a++)
#pragma unroll
                for (int c = 0; c < 8; c++) acc2[a][c] = ffma2(ar2[a], br2[c], acc2[a][c]);
        }
        __syncthreads();
    }
    int chunkbase = (b * NCHUNK + (n0 >> 8)) * COUT;
#pragma unroll
    for (int c = 0; c < 8; c++) {
        int o = o0 + ly + 16 * c;
        float bias = g_b3[o];
        float sev = g_se[chunkbase + o];
#pragma unroll
        for (int a = 0; a < 4; a++) {
            int n = n0 + 2 * lx + 32 * a;
            F2U cv; cv.u = acc2[a][c];
            float v0 = cv.f.x + bias;
            float v1 = cv.f.y + bias;
            v0 = fmaf(g_outpre[((size_t)b * Np + n) * COUT + o], sev, v0);
            v1 = fmaf(g_outpre[((size_t)b * Np + n + 1) * COUT + o], sev, v1);
            *(float2*)&out[((size_t)b * COUT + o) * Np + n] = make_float2(v0, v1);
        }
    }
}

// ---------------- launch ----------------
extern "C" void kernel_launch(void* const* d_in, const int* in_sizes, int n_in,
                              void* d_out, int out_size) {
    const float* x      = (const float*)d_in[0];
    const float* W_edge = (const float*)d_in[1];
    const float* bn1_g  = (const float*)d_in[2];
    const float* bn1_b  = (const float*)d_in[3];
    const float* bn1_m  = (const float*)d_in[4];
    const float* bn1_v  = (const float*)d_in[5];
    const float* w_att  = (const float*)d_in[6];
    const float* W_fuse = (const float*)d_in[7];
    const float* bn2_g  = (const float*)d_in[8];
    const float* bn2_b  = (const float*)d_in[9];
    const float* bn2_m  = (const float*)d_in[10];
    const float* bn2_v  = (const float*)d_in[11];
    const float* fc1_w  = (const float*)d_in[12];
    const float* fc1_b  = (const float*)d_in[13];
    const float* fc2_w  = (const float*)d_in[14];
    const float* fc2_b  = (const float*)d_in[15];
    const float* W_res  = (const float*)d_in[16];
    const float* bn3_g  = (const float*)d_in[17];
    const float* bn3_b  = (const float*)d_in[18];
    const float* bn3_m  = (const float*)d_in[19];
    const float* bn3_v  = (const float*)d_in[20];
    float* out = (float*)d_out;

    static const int d2_smem = 128 * TSTRIDE * (int)sizeof(float);  // 67584
    cudaFuncSetAttribute(d2_kernel, cudaFuncAttributeMaxDynamicSharedMemorySize, d2_smem);

    prep_kernel<<<64, 256>>>(W_edge, bn1_g, bn1_b, bn1_m, bn1_v,
                             W_fuse, bn2_g, bn2_b, bn2_m, bn2_v,
                             W_res, bn3_g, bn3_b, bn3_m, bn3_v);
    sq_kernel<<<dim3(Np / 256, Bn), 256>>>(x);
    d2_kernel<<<dim3(NT * (NT + 1) / 2, Bn), 256, d2_smem>>>(x);
    topk_kernel<<<dim3(Np / 8, Bn), 256>>>();
    ac_gemm<<<dim3(Np / 128, Bn, 2), 256>>>(x);
    attn_kernel<<<dim3(Np, Bn), 128>>>(w_att);
    se_sum_kernel<<<dim3(NCHUNK, Bn, 8), 256>>>();
    se_mlp_kernel<<<dim3(NCHUNK, Bn), 256>>>(fc1_w, fc1_b, fc2_w, fc2_b);
    final_kernel<<<dim3(Np / 128, COUT / 128, Bn), 256>>>(x, out);
}

// round 13
// speedup vs baseline: 1.0434x; 1.0434x over previous
#include <cuda_runtime.h>
#include <math.h>

#define Bn 4
#define CIN 128
#define Np 4096
#define Hd 128
#define COUT 256
#define Kn 16
#define SEH 64
#define NCHUNK 16
#define EPSB 1e-5f
#define NT 32   // 4096/128 tiles
#define TSTRIDE 130
#define WCAP 256

typedef unsigned long long u64;

// ---------------- scratch (static __device__, no allocations) ----------------
__device__ float g_sq[Bn * Np];
__device__ float g_d2[(size_t)Bn * Np * Np];        // 256 MiB
__device__ float g_rmin[(size_t)Bn * Np * NT];      // per-(row, tile) minima, 2 MiB
__device__ int   g_idx[Bn * Np * Kn];
__device__ float g_W1T[CIN * Hd];                   // [c][h]
__device__ float g_WCT[CIN * Hd];                   // [c][h]
__device__ float g_beff[Hd];
__device__ float g_WfuseT[Hd * COUT];               // [h][o]
__device__ float g_b2[COUT];
__device__ float g_WresT[CIN * COUT];               // [c][o]
__device__ float g_b3[COUT];
__device__ float g_A[(size_t)Bn * Np * Hd];
__device__ float g_C[(size_t)Bn * Np * Hd];
__device__ float g_outpre[(size_t)Bn * Np * COUT];
__device__ float g_separt[Bn * NCHUNK * 8 * COUT];
__device__ float g_se[Bn * NCHUNK * COUT];

__device__ __forceinline__ u64 ffma2(u64 a, u64 b, u64 c) {
    u64 d;
    asm("fma.rn.f32x2 %0, %1, %2, %3;" : "=l"(d) : "l"(a), "l"(b), "l"(c));
    return d;
}
union F2U { u64 u; float2 f; };

__device__ __forceinline__ u64 dup2(float v) {
    u64 r;
    asm("mov.b64 %0, {%1, %1};" : "=l"(r) : "f"(v));
    return r;
}

__device__ __forceinline__ u64 mk_key(float f, unsigned idx) {
    unsigned u = __float_as_uint(f);
    unsigned ord = (f < 0.f) ? ~u : (u | 0x80000000u);
    return ((u64)ord << 32) | idx;
}

// ---------------- prep: fold all BN into weights ----------------
__global__ void prep_kernel(const float* __restrict__ W_edge,
                            const float* __restrict__ g1, const float* __restrict__ b1,
                            const float* __restrict__ m1, const float* __restrict__ v1,
                            const float* __restrict__ W_fuse,
                            const float* __restrict__ g2, const float* __restrict__ b2,
                            const float* __restrict__ m2, const float* __restrict__ v2,
                            const float* __restrict__ W_res,
                            const float* __restrict__ g3, const float* __restrict__ b3,
                            const float* __restrict__ m3, const float* __restrict__ v3) {
    int i = blockIdx.x * blockDim.x + threadIdx.x;
    int stride = gridDim.x * blockDim.x;
    for (int t = i; t < CIN * Hd; t += stride) {
        int h = t % Hd, c = t / Hd;
        float s = g1[h] * rsqrtf(v1[h] + EPSB);
        float w1 = W_edge[h * (2 * CIN) + c];
        float w2 = W_edge[h * (2 * CIN) + CIN + c];
        g_W1T[t] = w1 * s;
        g_WCT[t] = (w2 - w1) * s;
    }
    for (int h = i; h < Hd; h += stride) {
        float s = g1[h] * rsqrtf(v1[h] + EPSB);
        g_beff[h] = b1[h] - m1[h] * s;
    }
    for (int t = i; t < Hd * COUT; t += stride) {
        int o = t % COUT, h = t / COUT;
        float s = g2[o] * rsqrtf(v2[o] + EPSB);
        g_WfuseT[t] = W_fuse[o * Hd + h] * s;
    }
    for (int o = i; o < COUT; o += stride) {
        float s2 = g2[o] * rsqrtf(v2[o] + EPSB);
        g_b2[o] = b2[o] - m2[o] * s2;
        float s3 = g3[o] * rsqrtf(v3[o] + EPSB);
        g_b3[o] = b3[o] - m3[o] * s3;
    }
    for (int t = i; t < CIN * COUT; t += stride) {
        int o = t % COUT, c = t / COUT;
        float s3 = g3[o] * rsqrtf(v3[o] + EPSB);
        g_WresT[t] = W_res[o * CIN + c] * s3;
    }
}

// ---------------- squared norms ----------------
__global__ void sq_kernel(const float* __restrict__ x) {
    int b = blockIdx.y;
    int n = blockIdx.x * 256 + threadIdx.x;
    const float* xb = x + (size_t)b * CIN * Np;
    float s = 0.f;
    for (int c = 0; c < CIN; c++) {
        float v = xb[(size_t)c * Np + n];
        s = fmaf(v, v, s);
    }
    g_sq[b * Np + n] = s;
}

// ---------------- symmetric d2 GEMM (FFMA2, non-dup A) + mirror + tile minima --
extern __shared__ float s_tile[];   // 128 * TSTRIDE floats

__global__ __launch_bounds__(256, 2) void d2_kernel(const float* __restrict__ x) {
    int b = blockIdx.y;
    int ti = 0, rem = blockIdx.x;
    while (rem >= NT - ti) { rem -= NT - ti; ti++; }
    int tj = ti + rem;
    int i0 = ti * 128, j0 = tj * 128;

    const float* xb = x + (size_t)b * CIN * Np;
    __shared__ __align__(16) float As[8][132];    // plain rows of i-tile
    __shared__ __align__(16) float Bs[8][128];
    __shared__ float colmin[128];
    u64 acc2[8][4];
#pragma unroll
    for (int a = 0; a < 8; a++)
#pragma unroll
        for (int c = 0; c < 4; c++) acc2[a][c] = 0ull;

    int tid = threadIdx.x;
    int lx = tid & 15, ly = tid >> 4;
    int loadc = tid >> 5, loadi = (tid & 31) * 4;

    for (int c0 = 0; c0 < CIN; c0 += 8) {
        const float* rowp = xb + (size_t)(c0 + loadc) * Np;
        *(float4*)&As[loadc][loadi] = *(const float4*)(rowp + i0 + loadi);
        *(float4*)&Bs[loadc][loadi] = *(const float4*)(rowp + j0 + loadi);
        __syncthreads();
#pragma unroll
        for (int k = 0; k < 8; k++) {
            u64 ar2[8], br2[4];
#pragma unroll
            for (int a = 0; a < 8; a++) ar2[a] = dup2(As[k][ly + 16 * a]);
#pragma unroll
            for (int c = 0; c < 4; c++) br2[c] = *(const u64*)&Bs[k][2 * lx + 32 * c];
#pragma unroll
            for (int a = 0; a < 8; a++)
#pragma unroll
                for (int c = 0; c < 4; c++) acc2[a][c] = ffma2(ar2[a], br2[c], acc2[a][c]);
        }
        __syncthreads();
    }
    // epilogue: d2 = sq_i + sq_j - 2*dot ; store + smem stage + per-row minima
    float sqi[8];
#pragma unroll
    for (int a = 0; a < 8; a++) sqi[a] = g_sq[b * Np + i0 + ly + 16 * a];
    float2 sqj2[4];
#pragma unroll
    for (int c = 0; c < 4; c++) sqj2[c] = *(const float2*)&g_sq[b * Np + j0 + 2 * lx + 32 * c];
    float* d2b = g_d2 + (size_t)b * Np * Np;
    float rmin[8];
#pragma unroll
    for (int a = 0; a < 8; a++) {
        int il = ly + 16 * a;
        float rm = INFINITY;
#pragma unroll
        for (int c = 0; c < 4; c++) {
            int jl = 2 * lx + 32 * c;
            F2U cv; cv.u = acc2[a][c];
            float v0 = sqi[a] + sqj2[c].x - 2.f * cv.f.x;
            float v1 = sqi[a] + sqj2[c].y - 2.f * cv.f.y;
            *(float2*)&s_tile[il * TSTRIDE + jl] = make_float2(v0, v1);
            *(float2*)&d2b[(size_t)(i0 + il) * Np + j0 + jl] = make_float2(v0, v1);
            rm = fminf(rm, fminf(v0, v1));
        }
        rmin[a] = rm;
    }
    // reduce row minima across the 16 lx lanes (lane = (ly&1)*16 + lx)
#pragma unroll
    for (int off = 1; off < 16; off <<= 1) {
#pragma unroll
        for (int a = 0; a < 8; a++) {
            float o = __shfl_xor_sync(0xffffffffu, rmin[a], off);
            rmin[a] = fminf(rmin[a], o);
        }
    }
    if (lx == 0) {
#pragma unroll
        for (int a = 0; a < 8; a++)
            g_rmin[((size_t)(b * Np + i0 + ly + 16 * a)) * NT + tj] = rmin[a];
    }
    if (ti != tj) {
        __syncthreads();
        // transposed store (coalesced over il)
        for (int idx = tid; idx < 128 * 128; idx += 256) {
            int jl = idx >> 7, il = idx & 127;
            d2b[(size_t)(j0 + jl) * Np + i0 + il] = s_tile[il * TSTRIDE + jl];
        }
        // column minima -> row minima of the mirrored rows (2 threads/col)
        {
            int col = tid & 127, half = tid >> 7;
            float cm = INFINITY;
            int il0 = half * 64;
            for (int il = il0; il < il0 + 64; il++)
                cm = fminf(cm, s_tile[il * TSTRIDE + col]);
            if (half == 0) colmin[col] = cm;
            __syncthreads();
            if (half == 1)
                g_rmin[((size_t)(b * Np + j0 + col)) * NT + ti] = fminf(cm, colmin[col]);
        }
    }
}

// ---------------- top-16: warp-per-row, tile-min threshold + tile skipping ----
__global__ __launch_bounds__(256, 8) void topk_kernel() {
    int tid = threadIdx.x;
    int lane = tid & 31, w = tid >> 5;
    int b = blockIdx.y;
    int n = blockIdx.x * 8 + w;
    const float* row = g_d2 + ((size_t)b * Np + n) * Np;

    __shared__ u64 wcand[8][WCAP];   // 16 KB, per-warp segments

    float rm = g_rmin[((size_t)(b * Np + n)) * NT + lane];
    {
        float v = rm;
#pragma unroll
        for (int k = 2; k <= 32; k <<= 1) {
#pragma unroll
            for (int j = k >> 1; j > 0; j >>= 1) {
                float o = __shfl_xor_sync(0xffffffffu, v, j);
                bool dirDesc = (lane & k) != 0;
                bool lower = (lane & j) == 0;
                bool takeMin = (lower != dirDesc);
                v = takeMin ? fminf(v, o) : fmaxf(v, o);
            }
        }
        float Tf_ = __shfl_sync(0xffffffffu, v, 15);
        unsigned tmask = __ballot_sync(0xffffffffu, rm <= Tf_);
        int cnt = 0;
        bool over = false;
        unsigned m = tmask;
        while (m) {
            int t = __ffs(m) - 1;
            m &= m - 1;
            float4 vv = *(const float4*)(row + t * 128 + lane * 4);
            float fv[4] = {vv.x, vv.y, vv.z, vv.w};
#pragma unroll
            for (int q = 0; q < 4; q++) {
                bool p = fv[q] <= Tf_;
                unsigned bm = __ballot_sync(0xffffffffu, p);
                if (p) {
                    int pos = cnt + __popc(bm & ((1u << lane) - 1u));
                    if (pos < WCAP) wcand[w][pos] = mk_key(fv[q], t * 128 + lane * 4 + q);
                    else over = true;
                }
                cnt += __popc(bm);
            }
        }
        over = __any_sync(0xffffffffu, over) || (cnt > WCAP);
        __syncwarp();

        int* outp = g_idx + ((b * Np + n) * Kn);
        if (!over) {
            for (int it = 0; it < Kn; it++) {
                u64 best = ~0ull; int bslot = -1;
                for (int s = lane; s < cnt; s += 32) {
                    u64 kk = wcand[w][s];
                    if (kk < best) { best = kk; bslot = s; }
                }
                u64 k = best;
#pragma unroll
                for (int off = 16; off; off >>= 1) {
                    u64 o = __shfl_xor_sync(0xffffffffu, k, off);
                    if (o < k) k = o;
                }
                if (lane == 0) outp[it] = (int)(unsigned)(k & 0xffffffffull);
                if (best == k && bslot >= 0) wcand[w][bslot] = ~0ull;
                __syncwarp();
            }
        } else {
            u64 last = 0;
            for (int it = 0; it < Kn; it++) {
                u64 best = ~0ull;
                for (int s = lane; s < Np; s += 32) {
                    u64 kk = mk_key(row[s], s);
                    if (kk > last && kk < best) best = kk;
                }
                u64 k = best;
#pragma unroll
                for (int off = 16; off; off >>= 1) {
                    u64 o = __shfl_xor_sync(0xffffffffu, k, off);
                    if (o < k) k = o;
                }
                if (lane == 0) outp[it] = (int)(unsigned)(k & 0xffffffffull);
                last = k;
            }
        }
    }
}

// ---------------- A/C projection GEMMs (FFMA2, non-dup A) ----------------
__global__ __launch_bounds__(256, 2) void ac_gemm(const float* __restrict__ x) {
    int b = blockIdx.y;
    int n0 = blockIdx.x * 128;
    int which = blockIdx.z;
    const float* WT = which ? g_WCT : g_W1T;  // [c][h], h contiguous
    const float* xb = x + (size_t)b * CIN * Np;
    __shared__ __align__(16) float As[8][132];
    __shared__ __align__(16) float Bs[8][128];
    u64 acc2[8][4];
#pragma unroll
    for (int a = 0; a < 8; a++)
#pragma unroll
        for (int c = 0; c < 4; c++) acc2[a][c] = 0ull;
    int tid = threadIdx.x;
    int lx = tid & 15, ly = tid >> 4;
    int loadc = tid >> 5, loadi = (tid & 31) * 4;
    for (int c0 = 0; c0 < CIN; c0 += 8) {
        *(float4*)&As[loadc][loadi] = *(const float4*)(xb + (size_t)(c0 + loadc) * Np + n0 + loadi);
        *(float4*)&Bs[loadc][loadi] = *(const float4*)(WT + (size_t)(c0 + loadc) * Hd + loadi);
        __syncthreads();
#pragma unroll
        for (int k = 0; k < 8; k++) {
            u64 ar2[8], br2[4];
#pragma unroll
            for (int a = 0; a < 8; a++) ar2[a] = dup2(As[k][ly + 16 * a]);
#pragma unroll
            for (int c = 0; c < 4; c++) br2[c] = *(const u64*)&Bs[k][2 * lx + 32 * c];
#pragma unroll
            for (int a = 0; a < 8; a++)
#pragma unroll
                for (int c = 0; c < 4; c++) acc2[a][c] = ffma2(ar2[a], br2[c], acc2[a][c]);
        }
        __syncthreads();
    }
    float* outb = which ? g_C : g_A;
#pragma unroll
    for (int a = 0; a < 8; a++) {
        int n = n0 + ly + 16 * a;
#pragma unroll
        for (int c = 0; c < 4; c++) {
            int h = 2 * lx + 32 * c;
            F2U cv; cv.u = acc2[a][c];
            float v0 = cv.f.x, v1 = cv.f.y;
            if (which) {
                float2 be = *(const float2*)&g_beff[h];
                v0 += be.x; v1 += be.y;
            }
            *(float2*)&outb[((size_t)b * Np + n) * Hd + h] = make_float2(v0, v1);
        }
    }
}

// ---------------- attention + aggregate + fuse (per query) ----------------
__global__ __launch_bounds__(128) void attn_kernel(const float* __restrict__ w_att) {
    int b = blockIdx.y, n = blockIdx.x;
    int tid = threadIdx.x;  // == h channel, 128
    __shared__ float shp[4][Kn];
    __shared__ float tk[Kn];
    __shared__ float aggs[Hd];
    const int* id = g_idx + ((b * Np + n) * Kn);
    const float* Ab = g_A + (size_t)b * Np * Hd;
    float Cc = g_C[((size_t)b * Np + n) * Hd + tid];
    float hk[Kn];
#pragma unroll
    for (int k = 0; k < Kn; k++) {
        int j = id[k];
        hk[k] = fmaxf(Ab[(size_t)j * Hd + tid] + Cc, 0.f);
    }
    float wa = w_att[tid];
    int lane = tid & 31, w = tid >> 5;
#pragma unroll
    for (int k = 0; k < Kn; k++) {
        float p = hk[k] * wa;
#pragma unroll
        for (int off = 16; off > 0; off >>= 1) p += __shfl_down_sync(0xffffffffu, p, off);
        if (lane == 0) shp[w][k] = p;
    }
    __syncthreads();
    if (tid < Kn) tk[tid] = shp[0][tid] + shp[1][tid] + shp[2][tid] + shp[3][tid];
    __syncthreads();
    float mx = -INFINITY;
#pragma unroll
    for (int k = 0; k < Kn; k++) mx = fmaxf(mx, tk[k]);
    float e[Kn]; float ssum = 0.f;
#pragma unroll
    for (int k = 0; k < Kn; k++) { e[k] = __expf(tk[k] - mx); ssum += e[k]; }
    float inv = 1.f / ssum;
    float agg = 0.f;
#pragma unroll
    for (int k = 0; k < Kn; k++) agg = fmaf(e[k], hk[k], agg);
    agg *= inv;
    aggs[tid] = agg;
    __syncthreads();
    float o0 = g_b2[tid], o1 = g_b2[tid + 128];
#pragma unroll 8
    for (int h = 0; h < Hd; h++) {
        float av = aggs[h];
        o0 = fmaf(av, g_WfuseT[h * COUT + tid], o0);
        o1 = fmaf(av, g_WfuseT[h * COUT + tid + 128], o1);
    }
    float* op = g_outpre + ((size_t)b * Np + n) * COUT;
    op[tid]       = fmaxf(o0, 0.f);
    op[tid + 128] = fmaxf(o1, 0.f);
}

// ---------------- SE stage 1: partial sums (512 blocks) ----------------
__global__ __launch_bounds__(256) void se_sum_kernel() {
    int b = blockIdx.y, ch = blockIdx.x, z = blockIdx.z;
    int tid = threadIdx.x;
    const float* op = g_outpre + ((size_t)b * Np + (size_t)ch * 256 + (size_t)z * 32) * COUT;
    float s = 0.f;
#pragma unroll 8
    for (int q = 0; q < 32; q++) s += op[(size_t)q * COUT + tid];
    g_separt[(((b * NCHUNK) + ch) * 8 + z) * COUT + tid] = s;
}

// ---------------- SE stage 2: combine + MLP ----------------
__global__ __launch_bounds__(256) void se_mlp_kernel(const float* __restrict__ fc1_w,
                                                     const float* __restrict__ fc1_b,
                                                     const float* __restrict__ fc2_w,
                                                     const float* __restrict__ fc2_b) {
    int b = blockIdx.y, ch = blockIdx.x;
    int tid = threadIdx.x;
    float s = 0.f;
#pragma unroll
    for (int z = 0; z < 8; z++)
        s += g_separt[(((b * NCHUNK) + ch) * 8 + z) * COUT + tid];
    __shared__ float mean[COUT];
    __shared__ float u[SEH];
    mean[tid] = s * (1.f / 256.f);
    __syncthreads();
    if (tid < SEH) {
        float acc = fc1_b[tid];
        for (int c = 0; c < COUT; c++) acc = fmaf(mean[c], fc1_w[tid * COUT + c], acc);
        u[tid] = fmaxf(acc, 0.f);
    }
    __syncthreads();
    float acc = fc2_b[tid];
#pragma unroll
    for (int j = 0; j < SEH; j++) acc = fmaf(u[j], fc2_w[tid * SEH + j], acc);
    g_se[(b * NCHUNK + ch) * COUT + tid] = 1.f / (1.f + __expf(-acc));
}

// ---------------- residual GEMM (FFMA2, non-dup B) + SE-scale + combine --------
__global__ __launch_bounds__(256, 2) void final_kernel(const float* __restrict__ x,
                                                       float* __restrict__ out) {
    int b = blockIdx.z;
    int n0 = blockIdx.x * 128;
    int o0 = blockIdx.y * 128;
    const float* xb = x + (size_t)b * CIN * Np;
    __shared__ __align__(16) float As[8][128];    // n-tile (pairs native)
    __shared__ __align__(16) float Bs[8][132];    // o-tile plain
    u64 acc2[4][8];  // [n-pair][o]
#pragma unroll
    for (int a = 0; a < 4; a++)
#pragma unroll
        for (int c = 0; c < 8; c++) acc2[a][c] = 0ull;
    int tid = threadIdx.x;
    int lx = tid & 15, ly = tid >> 4;  // lx -> n pairs, ly -> o
    int loadc = tid >> 5, loadi = (tid & 31) * 4;
    for (int c0 = 0; c0 < CIN; c0 += 8) {
        *(float4*)&As[loadc][loadi] = *(const float4*)(xb + (size_t)(c0 + loadc) * Np + n0 + loadi);
        *(float4*)&Bs[loadc][loadi] = *(const float4*)(g_WresT + (size_t)(c0 + loadc) * COUT + o0 + loadi);
        __syncthreads();
#pragma unroll
        for (int k = 0; k < 8; k++) {
            u64 ar2[4], br2[8];
#pragma unroll
            for (int a = 0; a < 4; a++) ar2[a] = *(const u64*)&As[k][2 * lx + 32 * a];
#pragma unroll
            for (int c = 0; c < 8; c++) br2[c] = dup2(Bs[k][ly + 16 * c]);
#pragma unroll
            for (int a = 0; a < 4; a++)
#pragma unroll
                for (int c = 0; c < 8; c++) acc2[a][c] = ffma2(ar2[a], br2[c], acc2[a][c]);
        }
        __syncthreads();
    }
    int chunkbase = (b * NCHUNK + (n0 >> 8)) * COUT;
#pragma unroll
    for (int c = 0; c < 8; c++) {
        int o = o0 + ly + 16 * c;
        float bias = g_b3[o];
        float sev = g_se[chunkbase + o];
#pragma unroll
        for (int a = 0; a < 4; a++) {
            int n = n0 + 2 * lx + 32 * a;
            F2U cv; cv.u = acc2[a][c];
            float v0 = cv.f.x + bias;
            float v1 = cv.f.y + bias;
            v0 = fmaf(g_outpre[((size_t)b * Np + n) * COUT + o], sev, v0);
            v1 = fmaf(g_outpre[((size_t)b * Np + n + 1) * COUT + o], sev, v1);
            *(float2*)&out[((size_t)b * COUT + o) * Np + n] = make_float2(v0, v1);
        }
    }
}

// ---------------- launch ----------------
extern "C" void kernel_launch(void* const* d_in, const int* in_sizes, int n_in,
                              void* d_out, int out_size) {
    const float* x      = (const float*)d_in[0];
    const float* W_edge = (const float*)d_in[1];
    const float* bn1_g  = (const float*)d_in[2];
    const float* bn1_b  = (const float*)d_in[3];
    const float* bn1_m  = (const float*)d_in[4];
    const float* bn1_v  = (const float*)d_in[5];
    const float* w_att  = (const float*)d_in[6];
    const float* W_fuse = (const float*)d_in[7];
    const float* bn2_g  = (const float*)d_in[8];
    const float* bn2_b  = (const float*)d_in[9];
    const float* bn2_m  = (const float*)d_in[10];
    const float* bn2_v  = (const float*)d_in[11];
    const float* fc1_w  = (const float*)d_in[12];
    const float* fc1_b  = (const float*)d_in[13];
    const float* fc2_w  = (const float*)d_in[14];
    const float* fc2_b  = (const float*)d_in[15];
    const float* W_res  = (const float*)d_in[16];
    const float* bn3_g  = (const float*)d_in[17];
    const float* bn3_b  = (const float*)d_in[18];
    const float* bn3_m  = (const float*)d_in[19];
    const float* bn3_v  = (const float*)d_in[20];
    float* out = (float*)d_out;

    static const int d2_smem = 128 * TSTRIDE * (int)sizeof(float);  // 66560
    cudaFuncSetAttribute(d2_kernel, cudaFuncAttributeMaxDynamicSharedMemorySize, d2_smem);

    prep_kernel<<<64, 256>>>(W_edge, bn1_g, bn1_b, bn1_m, bn1_v,
                             W_fuse, bn2_g, bn2_b, bn2_m, bn2_v,
                             W_res, bn3_g, bn3_b, bn3_m, bn3_v);
    sq_kernel<<<dim3(Np / 256, Bn), 256>>>(x);
    d2_kernel<<<dim3(NT * (NT + 1) / 2, Bn), 256, d2_smem>>>(x);
    topk_kernel<<<dim3(Np / 8, Bn), 256>>>();
    ac_gemm<<<dim3(Np / 128, Bn, 2), 256>>>(x);
    attn_kernel<<<dim3(Np, Bn), 128>>>(w_att);
    se_sum_kernel<<<dim3(NCHUNK, Bn, 8), 256>>>();
    se_mlp_kernel<<<dim3(NCHUNK, Bn), 256>>>(fc1_w, fc1_b, fc2_w, fc2_b);
    final_kernel<<<dim3(Np / 128, COUT / 128, Bn), 256>>>(x, out);
}

// round 14
// speedup vs baseline: 1.1384x; 1.0911x over previous
#include <cuda_runtime.h>
#include <math.h>

#define Bn 4
#define CIN 128
#define Np 4096
#define Hd 128
#define COUT 256
#define Kn 16
#define SEH 64
#define NCHUNK 16
#define EPSB 1e-5f
#define NT 32   // 4096/128 tiles
#define TSTRIDE 130
#define WCAP 256

typedef unsigned long long u64;

// ---------------- scratch (static __device__, no allocations) ----------------
__device__ float g_sq[Bn * Np];
__device__ float g_d2[(size_t)Bn * Np * Np];        // 256 MiB
__device__ float g_rmin[(size_t)Bn * Np * NT];      // per-(row, tile) minima, 2 MiB
__device__ int   g_idx[Bn * Np * Kn];
__device__ float g_W1T[CIN * Hd];                   // [c][h]
__device__ float g_WCT[CIN * Hd];                   // [c][h]
__device__ float g_beff[Hd];
__device__ float g_WfuseT[Hd * COUT];               // [h][o]
__device__ float g_b2[COUT];
__device__ float g_WresT[CIN * COUT];               // [c][o]
__device__ float g_b3[COUT];
__device__ float g_A[(size_t)Bn * Np * Hd];
__device__ float g_C[(size_t)Bn * Np * Hd];
__device__ float g_agg[(size_t)Bn * Np * Hd];       // attention-aggregated features
__device__ float g_outpre[(size_t)Bn * Np * COUT];
__device__ float g_separt[Bn * NCHUNK * 8 * COUT];
__device__ float g_se[Bn * NCHUNK * COUT];

__device__ __forceinline__ u64 ffma2(u64 a, u64 b, u64 c) {
    u64 d;
    asm("fma.rn.f32x2 %0, %1, %2, %3;" : "=l"(d) : "l"(a), "l"(b), "l"(c));
    return d;
}
union F2U { u64 u; float2 f; };

__device__ __forceinline__ u64 dup2(float v) {
    u64 r;
    asm("mov.b64 %0, {%1, %1};" : "=l"(r) : "f"(v));
    return r;
}

__device__ __forceinline__ u64 mk_key(float f, unsigned idx) {
    unsigned u = __float_as_uint(f);
    unsigned ord = (f < 0.f) ? ~u : (u | 0x80000000u);
    return ((u64)ord << 32) | idx;
}

// ---------------- prep: fold all BN into weights ----------------
__global__ void prep_kernel(const float* __restrict__ W_edge,
                            const float* __restrict__ g1, const float* __restrict__ b1,
                            const float* __restrict__ m1, const float* __restrict__ v1,
                            const float* __restrict__ W_fuse,
                            const float* __restrict__ g2, const float* __restrict__ b2,
                            const float* __restrict__ m2, const float* __restrict__ v2,
                            const float* __restrict__ W_res,
                            const float* __restrict__ g3, const float* __restrict__ b3,
                            const float* __restrict__ m3, const float* __restrict__ v3) {
    int i = blockIdx.x * blockDim.x + threadIdx.x;
    int stride = gridDim.x * blockDim.x;
    for (int t = i; t < CIN * Hd; t += stride) {
        int h = t % Hd, c = t / Hd;
        float s = g1[h] * rsqrtf(v1[h] + EPSB);
        float w1 = W_edge[h * (2 * CIN) + c];
        float w2 = W_edge[h * (2 * CIN) + CIN + c];
        g_W1T[t] = w1 * s;
        g_WCT[t] = (w2 - w1) * s;
    }
    for (int h = i; h < Hd; h += stride) {
        float s = g1[h] * rsqrtf(v1[h] + EPSB);
        g_beff[h] = b1[h] - m1[h] * s;
    }
    for (int t = i; t < Hd * COUT; t += stride) {
        int o = t % COUT, h = t / COUT;
        float s = g2[o] * rsqrtf(v2[o] + EPSB);
        g_WfuseT[t] = W_fuse[o * Hd + h] * s;
    }
    for (int o = i; o < COUT; o += stride) {
        float s2 = g2[o] * rsqrtf(v2[o] + EPSB);
        g_b2[o] = b2[o] - m2[o] * s2;
        float s3 = g3[o] * rsqrtf(v3[o] + EPSB);
        g_b3[o] = b3[o] - m3[o] * s3;
    }
    for (int t = i; t < CIN * COUT; t += stride) {
        int o = t % COUT, c = t / COUT;
        float s3 = g3[o] * rsqrtf(v3[o] + EPSB);
        g_WresT[t] = W_res[o * CIN + c] * s3;
    }
}

// ---------------- squared norms ----------------
__global__ void sq_kernel(const float* __restrict__ x) {
    int b = blockIdx.y;
    int n = blockIdx.x * 256 + threadIdx.x;
    const float* xb = x + (size_t)b * CIN * Np;
    float s = 0.f;
    for (int c = 0; c < CIN; c++) {
        float v = xb[(size_t)c * Np + n];
        s = fmaf(v, v, s);
    }
    g_sq[b * Np + n] = s;
}

// ---------------- symmetric d2 GEMM (FFMA2, non-dup A) + mirror + tile minima --
extern __shared__ float s_tile[];   // 128 * TSTRIDE floats

__global__ __launch_bounds__(256, 2) void d2_kernel(const float* __restrict__ x) {
    int b = blockIdx.y;
    int ti = 0, rem = blockIdx.x;
    while (rem >= NT - ti) { rem -= NT - ti; ti++; }
    int tj = ti + rem;
    int i0 = ti * 128, j0 = tj * 128;

    const float* xb = x + (size_t)b * CIN * Np;
    __shared__ __align__(16) float As[8][132];    // plain rows of i-tile
    __shared__ __align__(16) float Bs[8][128];
    __shared__ float colmin[128];
    u64 acc2[8][4];
#pragma unroll
    for (int a = 0; a < 8; a++)
#pragma unroll
        for (int c = 0; c < 4; c++) acc2[a][c] = 0ull;

    int tid = threadIdx.x;
    int lx = tid & 15, ly = tid >> 4;
    int loadc = tid >> 5, loadi = (tid & 31) * 4;

    for (int c0 = 0; c0 < CIN; c0 += 8) {
        const float* rowp = xb + (size_t)(c0 + loadc) * Np;
        *(float4*)&As[loadc][loadi] = *(const float4*)(rowp + i0 + loadi);
        *(float4*)&Bs[loadc][loadi] = *(const float4*)(rowp + j0 + loadi);
        __syncthreads();
#pragma unroll
        for (int k = 0; k < 8; k++) {
            u64 ar2[8], br2[4];
#pragma unroll
            for (int a = 0; a < 8; a++) ar2[a] = dup2(As[k][ly + 16 * a]);
#pragma unroll
            for (int c = 0; c < 4; c++) br2[c] = *(const u64*)&Bs[k][2 * lx + 32 * c];
#pragma unroll
            for (int a = 0; a < 8; a++)
#pragma unroll
                for (int c = 0; c < 4; c++) acc2[a][c] = ffma2(ar2[a], br2[c], acc2[a][c]);
        }
        __syncthreads();
    }
    // epilogue: d2 = sq_i + sq_j - 2*dot ; store + smem stage + per-row minima
    float sqi[8];
#pragma unroll
    for (int a = 0; a < 8; a++) sqi[a] = g_sq[b * Np + i0 + ly + 16 * a];
    float2 sqj2[4];
#pragma unroll
    for (int c = 0; c < 4; c++) sqj2[c] = *(const float2*)&g_sq[b * Np + j0 + 2 * lx + 32 * c];
    float* d2b = g_d2 + (size_t)b * Np * Np;
    float rmin[8];
#pragma unroll
    for (int a = 0; a < 8; a++) {
        int il = ly + 16 * a;
        float rm = INFINITY;
#pragma unroll
        for (int c = 0; c < 4; c++) {
            int jl = 2 * lx + 32 * c;
            F2U cv; cv.u = acc2[a][c];
            float v0 = sqi[a] + sqj2[c].x - 2.f * cv.f.x;
            float v1 = sqi[a] + sqj2[c].y - 2.f * cv.f.y;
            *(float2*)&s_tile[il * TSTRIDE + jl] = make_float2(v0, v1);
            *(float2*)&d2b[(size_t)(i0 + il) * Np + j0 + jl] = make_float2(v0, v1);
            rm = fminf(rm, fminf(v0, v1));
        }
        rmin[a] = rm;
    }
    // reduce row minima across the 16 lx lanes
#pragma unroll
    for (int off = 1; off < 16; off <<= 1) {
#pragma unroll
        for (int a = 0; a < 8; a++) {
            float o = __shfl_xor_sync(0xffffffffu, rmin[a], off);
            rmin[a] = fminf(rmin[a], o);
        }
    }
    if (lx == 0) {
#pragma unroll
        for (int a = 0; a < 8; a++)
            g_rmin[((size_t)(b * Np + i0 + ly + 16 * a)) * NT + tj] = rmin[a];
    }
    if (ti != tj) {
        __syncthreads();
        for (int idx = tid; idx < 128 * 128; idx += 256) {
            int jl = idx >> 7, il = idx & 127;
            d2b[(size_t)(j0 + jl) * Np + i0 + il] = s_tile[il * TSTRIDE + jl];
        }
        {
            int col = tid & 127, half = tid >> 7;
            float cm = INFINITY;
            int il0 = half * 64;
            for (int il = il0; il < il0 + 64; il++)
                cm = fminf(cm, s_tile[il * TSTRIDE + col]);
            if (half == 0) colmin[col] = cm;
            __syncthreads();
            if (half == 1)
                g_rmin[((size_t)(b * Np + j0 + col)) * NT + ti] = fminf(cm, colmin[col]);
        }
    }
}

// ---------------- top-16: warp-per-row, tile-min threshold + tile skipping ----
__global__ __launch_bounds__(256, 8) void topk_kernel() {
    int tid = threadIdx.x;
    int lane = tid & 31, w = tid >> 5;
    int b = blockIdx.y;
    int n = blockIdx.x * 8 + w;
    const float* row = g_d2 + ((size_t)b * Np + n) * Np;

    __shared__ u64 wcand[8][WCAP];   // 16 KB, per-warp segments

    float rm = g_rmin[((size_t)(b * Np + n)) * NT + lane];
    {
        float v = rm;
#pragma unroll
        for (int k = 2; k <= 32; k <<= 1) {
#pragma unroll
            for (int j = k >> 1; j > 0; j >>= 1) {
                float o = __shfl_xor_sync(0xffffffffu, v, j);
                bool dirDesc = (lane & k) != 0;
                bool lower = (lane & j) == 0;
                bool takeMin = (lower != dirDesc);
                v = takeMin ? fminf(v, o) : fmaxf(v, o);
            }
        }
        float Tf_ = __shfl_sync(0xffffffffu, v, 15);
        unsigned tmask = __ballot_sync(0xffffffffu, rm <= Tf_);
        int cnt = 0;
        bool over = false;
        unsigned m = tmask;
        while (m) {
            int t = __ffs(m) - 1;
            m &= m - 1;
            float4 vv = *(const float4*)(row + t * 128 + lane * 4);
            float fv[4] = {vv.x, vv.y, vv.z, vv.w};
#pragma unroll
            for (int q = 0; q < 4; q++) {
                bool p = fv[q] <= Tf_;
                unsigned bm = __ballot_sync(0xffffffffu, p);
                if (p) {
                    int pos = cnt + __popc(bm & ((1u << lane) - 1u));
                    if (pos < WCAP) wcand[w][pos] = mk_key(fv[q], t * 128 + lane * 4 + q);
                    else over = true;
                }
                cnt += __popc(bm);
            }
        }
        over = __any_sync(0xffffffffu, over) || (cnt > WCAP);
        __syncwarp();

        int* outp = g_idx + ((b * Np + n) * Kn);
        if (!over) {
            for (int it = 0; it < Kn; it++) {
                u64 best = ~0ull; int bslot = -1;
                for (int s = lane; s < cnt; s += 32) {
                    u64 kk = wcand[w][s];
                    if (kk < best) { best = kk; bslot = s; }
                }
                u64 k = best;
#pragma unroll
                for (int off = 16; off; off >>= 1) {
                    u64 o = __shfl_xor_sync(0xffffffffu, k, off);
                    if (o < k) k = o;
                }
                if (lane == 0) outp[it] = (int)(unsigned)(k & 0xffffffffull);
                if (best == k && bslot >= 0) wcand[w][bslot] = ~0ull;
                __syncwarp();
            }
        } else {
            u64 last = 0;
            for (int it = 0; it < Kn; it++) {
                u64 best = ~0ull;
                for (int s = lane; s < Np; s += 32) {
                    u64 kk = mk_key(row[s], s);
                    if (kk > last && kk < best) best = kk;
                }
                u64 k = best;
#pragma unroll
                for (int off = 16; off; off >>= 1) {
                    u64 o = __shfl_xor_sync(0xffffffffu, k, off);
                    if (o < k) k = o;
                }
                if (lane == 0) outp[it] = (int)(unsigned)(k & 0xffffffffull);
                last = k;
            }
        }
    }
}

// ---------------- A/C projection GEMMs (FFMA2, non-dup A) ----------------
__global__ __launch_bounds__(256, 2) void ac_gemm(const float* __restrict__ x) {
    int b = blockIdx.y;
    int n0 = blockIdx.x * 128;
    int which = blockIdx.z;
    const float* WT = which ? g_WCT : g_W1T;  // [c][h], h contiguous
    const float* xb = x + (size_t)b * CIN * Np;
    __shared__ __align__(16) float As[8][132];
    __shared__ __align__(16) float Bs[8][128];
    u64 acc2[8][4];
#pragma unroll
    for (int a = 0; a < 8; a++)
#pragma unroll
        for (int c = 0; c < 4; c++) acc2[a][c] = 0ull;
    int tid = threadIdx.x;
    int lx = tid & 15, ly = tid >> 4;
    int loadc = tid >> 5, loadi = (tid & 31) * 4;
    for (int c0 = 0; c0 < CIN; c0 += 8) {
        *(float4*)&As[loadc][loadi] = *(const float4*)(xb + (size_t)(c0 + loadc) * Np + n0 + loadi);
        *(float4*)&Bs[loadc][loadi] = *(const float4*)(WT + (size_t)(c0 + loadc) * Hd + loadi);
        __syncthreads();
#pragma unroll
        for (int k = 0; k < 8; k++) {
            u64 ar2[8], br2[4];
#pragma unroll
            for (int a = 0; a < 8; a++) ar2[a] = dup2(As[k][ly + 16 * a]);
#pragma unroll
            for (int c = 0; c < 4; c++) br2[c] = *(const u64*)&Bs[k][2 * lx + 32 * c];
#pragma unroll
            for (int a = 0; a < 8; a++)
#pragma unroll
                for (int c = 0; c < 4; c++) acc2[a][c] = ffma2(ar2[a], br2[c], acc2[a][c]);
        }
        __syncthreads();
    }
    float* outb = which ? g_C : g_A;
#pragma unroll
    for (int a = 0; a < 8; a++) {
        int n = n0 + ly + 16 * a;
#pragma unroll
        for (int c = 0; c < 4; c++) {
            int h = 2 * lx + 32 * c;
            F2U cv; cv.u = acc2[a][c];
            float v0 = cv.f.x, v1 = cv.f.y;
            if (which) {
                float2 be = *(const float2*)&g_beff[h];
                v0 += be.x; v1 += be.y;
            }
            *(float2*)&outb[((size_t)b * Np + n) * Hd + h] = make_float2(v0, v1);
        }
    }
}

// ---------------- attention + aggregate (per query), write g_agg ----------------
__global__ __launch_bounds__(128) void attn_agg_kernel(const float* __restrict__ w_att) {
    int b = blockIdx.y, n = blockIdx.x;
    int tid = threadIdx.x;  // == h channel, 128
    __shared__ float shp[4][Kn];
    __shared__ float tk[Kn];
    const int* id = g_idx + ((b * Np + n) * Kn);
    const float* Ab = g_A + (size_t)b * Np * Hd;
    float Cc = g_C[((size_t)b * Np + n) * Hd + tid];
    float hk[Kn];
#pragma unroll
    for (int k = 0; k < Kn; k++) {
        int j = id[k];
        hk[k] = fmaxf(Ab[(size_t)j * Hd + tid] + Cc, 0.f);
    }
    float wa = w_att[tid];
    int lane = tid & 31, w = tid >> 5;
#pragma unroll
    for (int k = 0; k < Kn; k++) {
        float p = hk[k] * wa;
#pragma unroll
        for (int off = 16; off > 0; off >>= 1) p += __shfl_down_sync(0xffffffffu, p, off);
        if (lane == 0) shp[w][k] = p;
    }
    __syncthreads();
    if (tid < Kn) tk[tid] = shp[0][tid] + shp[1][tid] + shp[2][tid] + shp[3][tid];
    __syncthreads();
    float mx = -INFINITY;
#pragma unroll
    for (int k = 0; k < Kn; k++) mx = fmaxf(mx, tk[k]);
    float e[Kn]; float ssum = 0.f;
#pragma unroll
    for (int k = 0; k < Kn; k++) { e[k] = __expf(tk[k] - mx); ssum += e[k]; }
    float inv = 1.f / ssum;
    float agg = 0.f;
#pragma unroll
    for (int k = 0; k < Kn; k++) agg = fmaf(e[k], hk[k], agg);
    g_agg[((size_t)b * Np + n) * Hd + tid] = agg * inv;
}

// ---------------- fuse GEMM: relu(agg @ WfuseT + b2) -> g_outpre ----------------
// bias pre-loaded into accumulators + ascending-h accumulation: bitwise
// identical to the previous per-thread fuse loop.
__global__ __launch_bounds__(256, 2) void fuse_gemm() {
    int b = blockIdx.z;
    int n0 = blockIdx.x * 128;
    int o0 = blockIdx.y * 128;
    __shared__ __align__(16) float As[8][132];    // [h][n] (transposed in)
    __shared__ __align__(16) float Bs[8][128];    // [h][o]
    u64 acc2[8][4];   // [a: n][c: o-pairs]
    int tid = threadIdx.x;
    int lx = tid & 15, ly = tid >> 4;
#pragma unroll
    for (int c = 0; c < 4; c++) {
        u64 bias = *(const u64*)&g_b2[o0 + 2 * lx + 32 * c];
#pragma unroll
        for (int a = 0; a < 8; a++) acc2[a][c] = bias;
    }
    int arow = tid >> 1, acol = tid & 1;
    int loadc = tid >> 5, loadi = (tid & 31) * 4;
    for (int c0 = 0; c0 < Hd; c0 += 8) {
        float4 va = *(const float4*)(g_agg + ((size_t)b * Np + n0 + arow) * Hd + c0 + 4 * acol);
        As[4 * acol + 0][arow] = va.x;
        As[4 * acol + 1][arow] = va.y;
        As[4 * acol + 2][arow] = va.z;
        As[4 * acol + 3][arow] = va.w;
        *(float4*)&Bs[loadc][loadi] = *(const float4*)(g_WfuseT + (size_t)(c0 + loadc) * COUT + o0 + loadi);
        __syncthreads();
#pragma unroll
        for (int k = 0; k < 8; k++) {
            u64 ar2[8], br2[4];
#pragma unroll
            for (int a = 0; a < 8; a++) ar2[a] = dup2(As[k][ly + 16 * a]);
#pragma unroll
            for (int c = 0; c < 4; c++) br2[c] = *(const u64*)&Bs[k][2 * lx + 32 * c];
#pragma unroll
            for (int a = 0; a < 8; a++)
#pragma unroll
                for (int c = 0; c < 4; c++) acc2[a][c] = ffma2(ar2[a], br2[c], acc2[a][c]);
        }
        __syncthreads();
    }
#pragma unroll
    for (int a = 0; a < 8; a++) {
        int n = n0 + ly + 16 * a;
#pragma unroll
        for (int c = 0; c < 4; c++) {
            int o = o0 + 2 * lx + 32 * c;
            F2U cv; cv.u = acc2[a][c];
            *(float2*)&g_outpre[((size_t)b * Np + n) * COUT + o] =
                make_float2(fmaxf(cv.f.x, 0.f), fmaxf(cv.f.y, 0.f));
        }
    }
}

// ---------------- SE stage 1: partial sums (512 blocks) ----------------
__global__ __launch_bounds__(256) void se_sum_kernel() {
    int b = blockIdx.y, ch = blockIdx.x, z = blockIdx.z;
    int tid = threadIdx.x;
    const float* op = g_outpre + ((size_t)b * Np + (size_t)ch * 256 + (size_t)z * 32) * COUT;
    float s = 0.f;
#pragma unroll 8
    for (int q = 0; q < 32; q++) s += op[(size_t)q * COUT + tid];
    g_separt[(((b * NCHUNK) + ch) * 8 + z) * COUT + tid] = s;
}

// ---------------- SE stage 2: combine + MLP ----------------
__global__ __launch_bounds__(256) void se_mlp_kernel(const float* __restrict__ fc1_w,
                                                     const float* __restrict__ fc1_b,
                                                     const float* __restrict__ fc2_w,
                                                     const float* __restrict__ fc2_b) {
    int b = blockIdx.y, ch = blockIdx.x;
    int tid = threadIdx.x;
    float s = 0.f;
#pragma unroll
    for (int z = 0; z < 8; z++)
        s += g_separt[(((b * NCHUNK) + ch) * 8 + z) * COUT + tid];
    __shared__ float mean[COUT];
    __shared__ float u[SEH];
    mean[tid] = s * (1.f / 256.f);
    __syncthreads();
    if (tid < SEH) {
        float acc = fc1_b[tid];
        for (int c = 0; c < COUT; c++) acc = fmaf(mean[c], fc1_w[tid * COUT + c], acc);
        u[tid] = fmaxf(acc, 0.f);
    }
    __syncthreads();
    float acc = fc2_b[tid];
#pragma unroll
    for (int j = 0; j < SEH; j++) acc = fmaf(u[j], fc2_w[tid * SEH + j], acc);
    g_se[(b * NCHUNK + ch) * COUT + tid] = 1.f / (1.f + __expf(-acc));
}

// ---------------- residual GEMM (FFMA2, non-dup B) + SE-scale + combine --------
__global__ __launch_bounds__(256, 2) void final_kernel(const float* __restrict__ x,
                                                       float* __restrict__ out) {
    int b = blockIdx.z;
    int n0 = blockIdx.x * 128;
    int o0 = blockIdx.y * 128;
    const float* xb = x + (size_t)b * CIN * Np;
    __shared__ __align__(16) float As[8][128];    // n-tile (pairs native)
    __shared__ __align__(16) float Bs[8][132];    // o-tile plain
    u64 acc2[4][8];  // [n-pair][o]
#pragma unroll
    for (int a = 0; a < 4; a++)
#pragma unroll
        for (int c = 0; c < 8; c++) acc2[a][c] = 0ull;
    int tid = threadIdx.x;
    int lx = tid & 15, ly = tid >> 4;  // lx -> n pairs, ly -> o
    int loadc = tid >> 5, loadi = (tid & 31) * 4;
    for (int c0 = 0; c0 < CIN; c0 += 8) {
        *(float4*)&As[loadc][loadi] = *(const float4*)(xb + (size_t)(c0 + loadc) * Np + n0 + loadi);
        *(float4*)&Bs[loadc][loadi] = *(const float4*)(g_WresT + (size_t)(c0 + loadc) * COUT + o0 + loadi);
        __syncthreads();
#pragma unroll
        for (int k = 0; k < 8; k++) {
            u64 ar2[4], br2[8];
#pragma unroll
            for (int a = 0; a < 4; a++) ar2[a] = *(const u64*)&As[k][2 * lx + 32 * a];
#pragma unroll
            for (int c = 0; c < 8; c++) br2[c] = dup2(Bs[k][ly + 16 * c]);
#pragma unroll
            for (int a = 0; a < 4; a++)
#pragma unroll
                for (int c = 0; c < 8; c++) acc2[a][c] = ffma2(ar2[a], br2[c], acc2[a][c]);
        }
        __syncthreads();
    }
    int chunkbase = (b * NCHUNK + (n0 >> 8)) * COUT;
#pragma unroll
    for (int c = 0; c < 8; c++) {
        int o = o0 + ly + 16 * c;
        float bias = g_b3[o];
        float sev = g_se[chunkbase + o];
#pragma unroll
        for (int a = 0; a < 4; a++) {
            int n = n0 + 2 * lx + 32 * a;
            F2U cv; cv.u = acc2[a][c];
            float v0 = cv.f.x + bias;
            float v1 = cv.f.y + bias;
            v0 = fmaf(g_outpre[((size_t)b * Np + n) * COUT + o], sev, v0);
            v1 = fmaf(g_outpre[((size_t)b * Np + n + 1) * COUT + o], sev, v1);
            *(float2*)&out[((size_t)b * COUT + o) * Np + n] = make_float2(v0, v1);
        }
    }
}

// ---------------- launch ----------------
extern "C" void kernel_launch(void* const* d_in, const int* in_sizes, int n_in,
                              void* d_out, int out_size) {
    const float* x      = (const float*)d_in[0];
    const float* W_edge = (const float*)d_in[1];
    const float* bn1_g  = (const float*)d_in[2];
    const float* bn1_b  = (const float*)d_in[3];
    const float* bn1_m  = (const float*)d_in[4];
    const float* bn1_v  = (const float*)d_in[5];
    const float* w_att  = (const float*)d_in[6];
    const float* W_fuse = (const float*)d_in[7];
    const float* bn2_g  = (const float*)d_in[8];
    const float* bn2_b  = (const float*)d_in[9];
    const float* bn2_m  = (const float*)d_in[10];
    const float* bn2_v  = (const float*)d_in[11];
    const float* fc1_w  = (const float*)d_in[12];
    const float* fc1_b  = (const float*)d_in[13];
    const float* fc2_w  = (const float*)d_in[14];
    const float* fc2_b  = (const float*)d_in[15];
    const float* W_res  = (const float*)d_in[16];
    const float* bn3_g  = (const float*)d_in[17];
    const float* bn3_b  = (const float*)d_in[18];
    const float* bn3_m  = (const float*)d_in[19];
    const float* bn3_v  = (const float*)d_in[20];
    float* out = (float*)d_out;

    static const int d2_smem = 128 * TSTRIDE * (int)sizeof(float);  // 66560
    cudaFuncSetAttribute(d2_kernel, cudaFuncAttributeMaxDynamicSharedMemorySize, d2_smem);

    prep_kernel<<<64, 256>>>(W_edge, bn1_g, bn1_b, bn1_m, bn1_v,
                             W_fuse, bn2_g, bn2_b, bn2_m, bn2_v,
                             W_res, bn3_g, bn3_b, bn3_m, bn3_v);
    sq_kernel<<<dim3(Np / 256, Bn), 256>>>(x);
    d2_kernel<<<dim3(NT * (NT + 1) / 2, Bn), 256, d2_smem>>>(x);
    topk_kernel<<<dim3(Np / 8, Bn), 256>>>();
    ac_gemm<<<dim3(Np / 128, Bn, 2), 256>>>(x);
    attn_agg_kernel<<<dim3(Np, Bn), 128>>>(w_att);
    fuse_gemm<<<dim3(Np / 128, COUT / 128, Bn), 256>>>();
    se_sum_kernel<<<dim3(NCHUNK, Bn, 8), 256>>>();
    se_mlp_kernel<<<dim3(NCHUNK, Bn), 256>>>(fc1_w, fc1_b, fc2_w, fc2_b);
    final_kernel<<<dim3(Np / 128, COUT / 128, Bn), 256>>>(x, out);
}

// round 16
// speedup vs baseline: 1.2157x; 1.0680x over previous
#include <cuda_runtime.h>
#include <cuda_fp16.h>
#include <math.h>
#include <stdint.h>

#define Bn 4
#define CIN 128
#define Np 4096
#define Hd 128
#define COUT 256
#define Kn 16
#define SEH 64
#define NCHUNK 16
#define EPSB 1e-5f
#define NT 32   // 4096/128 tiles
#define TSTRIDE 132
#define WCAP 256
#define PSTR 24   // halves per point-row in smem planes

typedef unsigned long long u64;

// ---------------- scratch (static __device__, no allocations) ----------------
__device__ float g_sq[Bn * Np];
__device__ float g_d2[(size_t)Bn * Np * Np];        // 256 MiB
__device__ float g_rmin[(size_t)Bn * Np * NT];      // per-(row, tile) minima
__device__ int   g_idx[Bn * Np * Kn];
__device__ __half g_xh[(size_t)Bn * Np * CIN];      // x hi, [b][n][k] point-major
__device__ __half g_xl[(size_t)Bn * Np * CIN];      // x lo
__device__ float g_W1T[CIN * Hd];                   // [c][h]
__device__ float g_WCT[CIN * Hd];                   // [c][h]
__device__ float g_beff[Hd];
__device__ float g_WfuseT[Hd * COUT];               // [h][o]
__device__ float g_b2[COUT];
__device__ float g_WresT[CIN * COUT];               // [c][o]
__device__ float g_b3[COUT];
__device__ float g_A[(size_t)Bn * Np * Hd];
__device__ float g_C[(size_t)Bn * Np * Hd];
__device__ float g_agg[(size_t)Bn * Np * Hd];
__device__ float g_outpre[(size_t)Bn * Np * COUT];
__device__ float g_separt[Bn * NCHUNK * 8 * COUT];
__device__ float g_se[Bn * NCHUNK * COUT];

__device__ __forceinline__ u64 ffma2(u64 a, u64 b, u64 c) {
    u64 d;
    asm("fma.rn.f32x2 %0, %1, %2, %3;" : "=l"(d) : "l"(a), "l"(b), "l"(c));
    return d;
}
union F2U { u64 u; float2 f; };

__device__ __forceinline__ u64 dup2(float v) {
    u64 r;
    asm("mov.b64 %0, {%1, %1};" : "=l"(r) : "f"(v));
    return r;
}

__device__ __forceinline__ u64 mk_key(float f, unsigned idx) {
    unsigned u = __float_as_uint(f);
    unsigned ord = (f < 0.f) ? ~u : (u | 0x80000000u);
    return ((u64)ord << 32) | idx;
}

__device__ __forceinline__ void mma_f16(float* d, const unsigned* a,
                                        unsigned b0, unsigned b1) {
    asm volatile(
        "mma.sync.aligned.m16n8k16.row.col.f32.f16.f16.f32 "
        "{%0,%1,%2,%3}, {%4,%5,%6,%7}, {%8,%9}, {%0,%1,%2,%3};"
        : "+f"(d[0]), "+f"(d[1]), "+f"(d[2]), "+f"(d[3])
        : "r"(a[0]), "r"(a[1]), "r"(a[2]), "r"(a[3]), "r"(b0), "r"(b1));
}

// ---------------- prep: fold all BN into weights ----------------
__global__ void prep_kernel(const float* __restrict__ W_edge,
                            const float* __restrict__ g1, const float* __restrict__ b1,
                            const float* __restrict__ m1, const float* __restrict__ v1,
                            const float* __restrict__ W_fuse,
                            const float* __restrict__ g2, const float* __restrict__ b2,
                            const float* __restrict__ m2, const float* __restrict__ v2,
                            const float* __restrict__ W_res,
                            const float* __restrict__ g3, const float* __restrict__ b3,
                            const float* __restrict__ m3, const float* __restrict__ v3) {
    int i = blockIdx.x * blockDim.x + threadIdx.x;
    int stride = gridDim.x * blockDim.x;
    for (int t = i; t < CIN * Hd; t += stride) {
        int h = t % Hd, c = t / Hd;
        float s = g1[h] * rsqrtf(v1[h] + EPSB);
        float w1 = W_edge[h * (2 * CIN) + c];
        float w2 = W_edge[h * (2 * CIN) + CIN + c];
        g_W1T[t] = w1 * s;
        g_WCT[t] = (w2 - w1) * s;
    }
    for (int h = i; h < Hd; h += stride) {
        float s = g1[h] * rsqrtf(v1[h] + EPSB);
        g_beff[h] = b1[h] - m1[h] * s;
    }
    for (int t = i; t < Hd * COUT; t += stride) {
        int o = t % COUT, h = t / COUT;
        float s = g2[o] * rsqrtf(v2[o] + EPSB);
        g_WfuseT[t] = W_fuse[o * Hd + h] * s;
    }
    for (int o = i; o < COUT; o += stride) {
        float s2 = g2[o] * rsqrtf(v2[o] + EPSB);
        g_b2[o] = b2[o] - m2[o] * s2;
        float s3 = g3[o] * rsqrtf(v3[o] + EPSB);
        g_b3[o] = b3[o] - m3[o] * s3;
    }
    for (int t = i; t < CIN * COUT; t += stride) {
        int o = t % COUT, c = t / COUT;
        float s3 = g3[o] * rsqrtf(v3[o] + EPSB);
        g_WresT[t] = W_res[o * CIN + c] * s3;
    }
}

// ---------------- squared norms ----------------
__global__ void sq_kernel(const float* __restrict__ x) {
    int b = blockIdx.y;
    int n = blockIdx.x * 256 + threadIdx.x;
    const float* xb = x + (size_t)b * CIN * Np;
    float s = 0.f;
    for (int c = 0; c < CIN; c++) {
        float v = xb[(size_t)c * Np + n];
        s = fmaf(v, v, s);
    }
    g_sq[b * Np + n] = s;
}

// ---------------- fp16 hi/lo split + transpose to [n][k] ----------------
__global__ void cvt_kernel(const float* __restrict__ x) {
    int b = blockIdx.z;
    int n0 = blockIdx.x * 32, k0 = blockIdx.y * 32;
    int tx = threadIdx.x, ty = threadIdx.y;   // (32, 8)
    const float* xb = x + (size_t)b * CIN * Np;
    __shared__ __half th[32][34], tl[32][34];   // [n][k] tile
    for (int r = ty; r < 32; r += 8) {
        float v = xb[(size_t)(k0 + r) * Np + n0 + tx];
        __half h = __float2half(v);
        __half l = __float2half(v - __half2float(h));
        th[tx][r] = h;
        tl[tx][r] = l;
    }
    __syncthreads();
    for (int r = ty; r < 32; r += 8) {
        g_xh[((size_t)b * Np + n0 + r) * CIN + k0 + tx] = th[r][tx];
        g_xl[((size_t)b * Np + n0 + r) * CIN + k0 + tx] = tl[r][tx];
    }
}

// ---------------- symmetric d2 via fp16-split m16n8k16 HMMA -------------------
// dot = hi*hi' + hi*lo' + lo*hi'; dropped lo*lo' <= 2^-22 rel. d2 only selects
// neighbor indices (values unused downstream) -> selection provably unchanged.
extern __shared__ __align__(16) char s_raw[];

__global__ __launch_bounds__(256, 2) void d2_kernel() {
    int b = blockIdx.y;
    int ti = 0, rem = blockIdx.x;
    while (rem >= NT - ti) { rem -= NT - ti; ti++; }
    int tj = ti + rem;
    int i0 = ti * 128, j0 = tj * 128;

    __half* sAh = (__half*)s_raw;             // 128*PSTR halves = 6KB
    __half* sAl = sAh + 128 * PSTR;
    __half* sBh = sAl + 128 * PSTR;
    __half* sBl = sBh + 128 * PSTR;
    float* s_tile = (float*)s_raw;            // epilogue overlay (67.6KB)
    __shared__ float s_sqi[128], s_sqj[128], colmin[128];

    int tid = threadIdx.x;
    int lane = tid & 31, w = tid >> 5;
    if (tid < 128) s_sqi[tid] = g_sq[b * Np + i0 + tid];
    else           s_sqj[tid - 128] = g_sq[b * Np + j0 + tid - 128];

    float acc[2][8][4];
#pragma unroll
    for (int s = 0; s < 2; s++)
#pragma unroll
        for (int j = 0; j < 8; j++)
#pragma unroll
            for (int q = 0; q < 4; q++) acc[s][j][q] = 0.f;

    int m0w = (w >> 1) * 32;
    int n0w = (w & 1) * 64;
    int g = lane >> 2, t = lane & 3;
    int lp = tid >> 1, lseg = (tid & 1) * 8;   // staging: point, 8-half segment

    const __half* xhA = g_xh + ((size_t)b * Np + i0 + lp) * CIN + lseg;
    const __half* xlA = g_xl + ((size_t)b * Np + i0 + lp) * CIN + lseg;
    const __half* xhB = g_xh + ((size_t)b * Np + j0 + lp) * CIN + lseg;
    const __half* xlB = g_xl + ((size_t)b * Np + j0 + lp) * CIN + lseg;
    int sb = lp * PSTR + lseg;

    for (int c0 = 0; c0 < CIN; c0 += 16) {
        __syncthreads();
        *(uint4*)&sAh[sb] = *(const uint4*)(xhA + c0);
        *(uint4*)&sAl[sb] = *(const uint4*)(xlA + c0);
        *(uint4*)&sBh[sb] = *(const uint4*)(xhB + c0);
        *(uint4*)&sBl[sb] = *(const uint4*)(xlB + c0);
        __syncthreads();

        unsigned ah[2][4], al[2][4];
#pragma unroll
        for (int s = 0; s < 2; s++) {
            int base = (m0w + 16 * s + g) * PSTR;
            ah[s][0] = *(const unsigned*)&sAh[base + 2 * t];
            ah[s][1] = *(const unsigned*)&sAh[base + 8 * PSTR + 2 * t];
            ah[s][2] = *(const unsigned*)&sAh[base + 2 * t + 8];
            ah[s][3] = *(const unsigned*)&sAh[base + 8 * PSTR + 2 * t + 8];
            al[s][0] = *(const unsigned*)&sAl[base + 2 * t];
            al[s][1] = *(const unsigned*)&sAl[base + 8 * PSTR + 2 * t];
            al[s][2] = *(const unsigned*)&sAl[base + 2 * t + 8];
            al[s][3] = *(const unsigned*)&sAl[base + 8 * PSTR + 2 * t + 8];
        }
#pragma unroll
        for (int j = 0; j < 8; j++) {
            int bbase = (n0w + 8 * j + g) * PSTR;
            unsigned bh0 = *(const unsigned*)&sBh[bbase + 2 * t];
            unsigned bh1 = *(const unsigned*)&sBh[bbase + 2 * t + 8];
            unsigned bl0 = *(const unsigned*)&sBl[bbase + 2 * t];
            unsigned bl1 = *(const unsigned*)&sBl[bbase + 2 * t + 8];
#pragma unroll
            for (int s = 0; s < 2; s++) {
                mma_f16(acc[s][j], ah[s], bh0, bh1);
                mma_f16(acc[s][j], ah[s], bl0, bl1);
                mma_f16(acc[s][j], al[s], bh0, bh1);
            }
        }
    }
    __syncthreads();   // planes dead; s_tile staging begins

    // stage d2 = sq_i + sq_j - 2*dot into s_tile
#pragma unroll
    for (int s = 0; s < 2; s++) {
        int r = m0w + 16 * s + g;
        float sq0 = s_sqi[r], sq1 = s_sqi[r + 8];
#pragma unroll
        for (int j = 0; j < 8; j++) {
            int c = n0w + 8 * j + 2 * t;
            float sj0 = s_sqj[c], sj1 = s_sqj[c + 1];
            *(float2*)&s_tile[r * TSTRIDE + c] =
                make_float2(sq0 + sj0 - 2.f * acc[s][j][0],
                            sq0 + sj1 - 2.f * acc[s][j][1]);
            *(float2*)&s_tile[(r + 8) * TSTRIDE + c] =
                make_float2(sq1 + sj0 - 2.f * acc[s][j][2],
                            sq1 + sj1 - 2.f * acc[s][j][3]);
        }
    }
    __syncthreads();

    float* d2b = g_d2 + (size_t)b * Np * Np;
    // direct store (coalesced float4) + fused row minima
    {
        int r = tid >> 1, h = tid & 1;
        const float4* src = (const float4*)(s_tile + r * TSTRIDE + h * 64);
        float4* dst = (float4*)(d2b + (size_t)(i0 + r) * Np + j0 + h * 64);
        float rm = INFINITY;
#pragma unroll
        for (int q = 0; q < 16; q++) {
            float4 v = src[q];
            dst[q] = v;
            rm = fminf(rm, fminf(fminf(v.x, v.y), fminf(v.z, v.w)));
        }
        float o = __shfl_xor_sync(0xffffffffu, rm, 1);
        rm = fminf(rm, o);
        if (h == 0) g_rmin[((size_t)(b * Np + i0 + r)) * NT + tj] = rm;
    }
    if (ti != tj) {
        // transposed store (coalesced over il)
        for (int idx = tid; idx < 128 * 128; idx += 256) {
            int jl = idx >> 7, il = idx & 127;
            d2b[(size_t)(j0 + jl) * Np + i0 + il] = s_tile[il * TSTRIDE + jl];
        }
        // column minima -> row minima of the mirrored rows (2 threads/col)
        {
            int col = tid & 127, half = tid >> 7;
            float cm = INFINITY;
            int il0 = half * 64;
            for (int il = il0; il < il0 + 64; il++)
                cm = fminf(cm, s_tile[il * TSTRIDE + col]);
            if (half == 0) colmin[col] = cm;
            __syncthreads();
            if (half == 1)
                g_rmin[((size_t)(b * Np + j0 + col)) * NT + ti] = fminf(cm, colmin[col]);
        }
    }
}

// ---------------- top-16: warp-per-row, tile-min threshold + tile skipping ----
__global__ __launch_bounds__(256, 8) void topk_kernel() {
    int tid = threadIdx.x;
    int lane = tid & 31, w = tid >> 5;
    int b = blockIdx.y;
    int n = blockIdx.x * 8 + w;
    const float* row = g_d2 + ((size_t)b * Np + n) * Np;

    __shared__ u64 wcand[8][WCAP];   // 16 KB, per-warp segments

    float rm = g_rmin[((size_t)(b * Np + n)) * NT + lane];
    {
        float v = rm;
#pragma unroll
        for (int k = 2; k <= 32; k <<= 1) {
#pragma unroll
            for (int j = k >> 1; j > 0; j >>= 1) {
                float o = __shfl_xor_sync(0xffffffffu, v, j);
                bool dirDesc = (lane & k) != 0;
                bool lower = (lane & j) == 0;
                bool takeMin = (lower != dirDesc);
                v = takeMin ? fminf(v, o) : fmaxf(v, o);
            }
        }
        float Tf_ = __shfl_sync(0xffffffffu, v, 15);
        unsigned tmask = __ballot_sync(0xffffffffu, rm <= Tf_);
        int cnt = 0;
        bool over = false;
        unsigned m = tmask;
        while (m) {
            int t = __ffs(m) - 1;
            m &= m - 1;
            float4 vv = *(const float4*)(row + t * 128 + lane * 4);
            float fv[4] = {vv.x, vv.y, vv.z, vv.w};
#pragma unroll
            for (int q = 0; q < 4; q++) {
                bool p = fv[q] <= Tf_;
                unsigned bm = __ballot_sync(0xffffffffu, p);
                if (p) {
                    int pos = cnt + __popc(bm & ((1u << lane) - 1u));
                    if (pos < WCAP) wcand[w][pos] = mk_key(fv[q], t * 128 + lane * 4 + q);
                    else over = true;
                }
                cnt += __popc(bm);
            }
        }
        over = __any_sync(0xffffffffu, over) || (cnt > WCAP);
        __syncwarp();

        int* outp = g_idx + ((b * Np + n) * Kn);
        if (!over) {
            for (int it = 0; it < Kn; it++) {
                u64 best = ~0ull; int bslot = -1;
                for (int s = lane; s < cnt; s += 32) {
                    u64 kk = wcand[w][s];
                    if (kk < best) { best = kk; bslot = s; }
                }
                u64 k = best;
#pragma unroll
                for (int off = 16; off; off >>= 1) {
                    u64 o = __shfl_xor_sync(0xffffffffu, k, off);
                    if (o < k) k = o;
                }
                if (lane == 0) outp[it] = (int)(unsigned)(k & 0xffffffffull);
                if (best == k && bslot >= 0) wcand[w][bslot] = ~0ull;
                __syncwarp();
            }
        } else {
            u64 last = 0;
            for (int it = 0; it < Kn; it++) {
                u64 best = ~0ull;
                for (int s = lane; s < Np; s += 32) {
                    u64 kk = mk_key(row[s], s);
                    if (kk > last && kk < best) best = kk;
                }
                u64 k = best;
#pragma unroll
                for (int off = 16; off; off >>= 1) {
                    u64 o = __shfl_xor_sync(0xffffffffu, k, off);
                    if (o < k) k = o;
                }
                if (lane == 0) outp[it] = (int)(unsigned)(k & 0xffffffffull);
                last = k;
            }
        }
    }
}

// ---------------- A/C projection GEMMs (FFMA2, non-dup A) ----------------
__global__ __launch_bounds__(256, 2) void ac_gemm(const float* __restrict__ x) {
    int b = blockIdx.y;
    int n0 = blockIdx.x * 128;
    int which = blockIdx.z;
    const float* WT = which ? g_WCT : g_W1T;  // [c][h], h contiguous
    const float* xb = x + (size_t)b * CIN * Np;
    __shared__ __align__(16) float As[8][132];
    __shared__ __align__(16) float Bs[8][128];
    u64 acc2[8][4];
#pragma unroll
    for (int a = 0; a < 8; a++)
#pragma unroll
        for (int c = 0; c < 4; c++) acc2[a][c] = 0ull;
    int tid = threadIdx.x;
    int lx = tid & 15, ly = tid >> 4;
    int loadc = tid >> 5, loadi = (tid & 31) * 4;
    for (int c0 = 0; c0 < CIN; c0 += 8) {
        *(float4*)&As[loadc][loadi] = *(const float4*)(xb + (size_t)(c0 + loadc) * Np + n0 + loadi);
        *(float4*)&Bs[loadc][loadi] = *(const float4*)(WT + (size_t)(c0 + loadc) * Hd + loadi);
        __syncthreads();
#pragma unroll
        for (int k = 0; k < 8; k++) {
            u64 ar2[8], br2[4];
#pragma unroll
            for (int a = 0; a < 8; a++) ar2[a] = dup2(As[k][ly + 16 * a]);
#pragma unroll
            for (int c = 0; c < 4; c++) br2[c] = *(const u64*)&Bs[k][2 * lx + 32 * c];
#pragma unroll
            for (int a = 0; a < 8; a++)
#pragma unroll
                for (int c = 0; c < 4; c++) acc2[a][c] = ffma2(ar2[a], br2[c], acc2[a][c]);
        }
        __syncthreads();
    }
    float* outb = which ? g_C : g_A;
#pragma unroll
    for (int a = 0; a < 8; a++) {
        int n = n0 + ly + 16 * a;
#pragma unroll
        for (int c = 0; c < 4; c++) {
            int h = 2 * lx + 32 * c;
            F2U cv; cv.u = acc2[a][c];
            float v0 = cv.f.x, v1 = cv.f.y;
            if (which) {
                float2 be = *(const float2*)&g_beff[h];
                v0 += be.x; v1 += be.y;
            }
            *(float2*)&outb[((size_t)b * Np + n) * Hd + h] = make_float2(v0, v1);
        }
    }
}

// ---------------- attention + aggregate (per query), write g_agg ----------------
__global__ __launch_bounds__(128) void attn_agg_kernel(const float* __restrict__ w_att) {
    int b = blockIdx.y, n = blockIdx.x;
    int tid = threadIdx.x;  // == h channel, 128
    __shared__ float shp[4][Kn];
    __shared__ float tk[Kn];
    const int* id = g_idx + ((b * Np + n) * Kn);
    const float* Ab = g_A + (size_t)b * Np * Hd;
    float Cc = g_C[((size_t)b * Np + n) * Hd + tid];
    float hk[Kn];
#pragma unroll
    for (int k = 0; k < Kn; k++) {
        int j = id[k];
        hk[k] = fmaxf(Ab[(size_t)j * Hd + tid] + Cc, 0.f);
    }
    float wa = w_att[tid];
    int lane = tid & 31, w = tid >> 5;
#pragma unroll
    for (int k = 0; k < Kn; k++) {
        float p = hk[k] * wa;
#pragma unroll
        for (int off = 16; off > 0; off >>= 1) p += __shfl_down_sync(0xffffffffu, p, off);
        if (lane == 0) shp[w][k] = p;
    }
    __syncthreads();
    if (tid < Kn) tk[tid] = shp[0][tid] + shp[1][tid] + shp[2][tid] + shp[3][tid];
    __syncthreads();
    float mx = -INFINITY;
#pragma unroll
    for (int k = 0; k < Kn; k++) mx = fmaxf(mx, tk[k]);
    float e[Kn]; float ssum = 0.f;
#pragma unroll
    for (int k = 0; k < Kn; k++) { e[k] = __expf(tk[k] - mx); ssum += e[k]; }
    float inv = 1.f / ssum;
    float agg = 0.f;
#pragma unroll
    for (int k = 0; k < Kn; k++) agg = fmaf(e[k], hk[k], agg);
    g_agg[((size_t)b * Np + n) * Hd + tid] = agg * inv;
}

// ---------------- fuse GEMM: relu(agg @ WfuseT + b2) -> g_outpre ----------------
__global__ __launch_bounds__(256, 2) void fuse_gemm() {
    int b = blockIdx.z;
    int n0 = blockIdx.x * 128;
    int o0 = blockIdx.y * 128;
    __shared__ __align__(16) float As[8][132];    // [h][n] (transposed in)
    __shared__ __align__(16) float Bs[8][128];    // [h][o]
    u64 acc2[8][4];   // [a: n][c: o-pairs]
    int tid = threadIdx.x;
    int lx = tid & 15, ly = tid >> 4;
#pragma unroll
    for (int c = 0; c < 4; c++) {
        u64 bias = *(const u64*)&g_b2[o0 + 2 * lx + 32 * c];
#pragma unroll
        for (int a = 0; a < 8; a++) acc2[a][c] = bias;
    }
    int arow = tid >> 1, acol = tid & 1;
    int loadc = tid >> 5, loadi = (tid & 31) * 4;
    for (int c0 = 0; c0 < Hd; c0 += 8) {
        float4 va = *(const float4*)(g_agg + ((size_t)b * Np + n0 + arow) * Hd + c0 + 4 * acol);
        As[4 * acol + 0][arow] = va.x;
        As[4 * acol + 1][arow] = va.y;
        As[4 * acol + 2][arow] = va.z;
        As[4 * acol + 3][arow] = va.w;
        *(float4*)&Bs[loadc][loadi] = *(const float4*)(g_WfuseT + (size_t)(c0 + loadc) * COUT + o0 + loadi);
        __syncthreads();
#pragma unroll
        for (int k = 0; k < 8; k++) {
            u64 ar2[8], br2[4];
#pragma unroll
            for (int a = 0; a < 8; a++) ar2[a] = dup2(As[k][ly + 16 * a]);
#pragma unroll
            for (int c = 0; c < 4; c++) br2[c] = *(const u64*)&Bs[k][2 * lx + 32 * c];
#pragma unroll
            for (int a = 0; a < 8; a++)
#pragma unroll
                for (int c = 0; c < 4; c++) acc2[a][c] = ffma2(ar2[a], br2[c], acc2[a][c]);
        }
        __syncthreads();
    }
#pragma unroll
    for (int a = 0; a < 8; a++) {
        int n = n0 + ly + 16 * a;
#pragma unroll
        for (int c = 0; c < 4; c++) {
            int o = o0 + 2 * lx + 32 * c;
            F2U cv; cv.u = acc2[a][c];
            *(float2*)&g_outpre[((size_t)b * Np + n) * COUT + o] =
                make_float2(fmaxf(cv.f.x, 0.f), fmaxf(cv.f.y, 0.f));
        }
    }
}

// ---------------- SE stage 1: partial sums (512 blocks) ----------------
__global__ __launch_bounds__(256) void se_sum_kernel() {
    int b = blockIdx.y, ch = blockIdx.x, z = blockIdx.z;
    int tid = threadIdx.x;
    const float* op = g_outpre + ((size_t)b * Np + (size_t)ch * 256 + (size_t)z * 32) * COUT;
    float s = 0.f;
#pragma unroll 8
    for (int q = 0; q < 32; q++) s += op[(size_t)q * COUT + tid];
    g_separt[(((b * NCHUNK) + ch) * 8 + z) * COUT + tid] = s;
}

// ---------------- SE stage 2: combine + MLP ----------------
__global__ __launch_bounds__(256) void se_mlp_kernel(const float* __restrict__ fc1_w,
                                                     const float* __restrict__ fc1_b,
                                                     const float* __restrict__ fc2_w,
                                                     const float* __restrict__ fc2_b) {
    int b = blockIdx.y, ch = blockIdx.x;
    int tid = threadIdx.x;
    float s = 0.f;
#pragma unroll
    for (int z = 0; z < 8; z++)
        s += g_separt[(((b * NCHUNK) + ch) * 8 + z) * COUT + tid];
    __shared__ float mean[COUT];
    __shared__ float u[SEH];
    mean[tid] = s * (1.f / 256.f);
    __syncthreads();
    if (tid < SEH) {
        float acc = fc1_b[tid];
        for (int c = 0; c < COUT; c++) acc = fmaf(mean[c], fc1_w[tid * COUT + c], acc);
        u[tid] = fmaxf(acc, 0.f);
    }
    __syncthreads();
    float acc = fc2_b[tid];
#pragma unroll
    for (int j = 0; j < SEH; j++) acc = fmaf(u[j], fc2_w[tid * SEH + j], acc);
    g_se[(b * NCHUNK + ch) * COUT + tid] = 1.f / (1.f + __expf(-acc));
}

// ---------------- residual GEMM (FFMA2, non-dup B) + SE-scale + combine --------
__global__ __launch_bounds__(256, 2) void final_kernel(const float* __restrict__ x,
                                                       float* __restrict__ out) {
    int b = blockIdx.z;
    int n0 = blockIdx.x * 128;
    int o0 = blockIdx.y * 128;
    const float* xb = x + (size_t)b * CIN * Np;
    __shared__ __align__(16) float As[8][128];    // n-tile (pairs native)
    __shared__ __align__(16) float Bs[8][132];    // o-tile plain
    u64 acc2[4][8];  // [n-pair][o]
#pragma unroll
    for (int a = 0; a < 4; a++)
#pragma unroll
        for (int c = 0; c < 8; c++) acc2[a][c] = 0ull;
    int tid = threadIdx.x;
    int lx = tid & 15, ly = tid >> 4;  // lx -> n pairs, ly -> o
    int loadc = tid >> 5, loadi = (tid & 31) * 4;
    for (int c0 = 0; c0 < CIN; c0 += 8) {
        *(float4*)&As[loadc][loadi] = *(const float4*)(xb + (size_t)(c0 + loadc) * Np + n0 + loadi);
        *(float4*)&Bs[loadc][loadi] = *(const float4*)(g_WresT + (size_t)(c0 + loadc) * COUT + o0 + loadi);
        __syncthreads();
#pragma unroll
        for (int k = 0; k < 8; k++) {
            u64 ar2[4], br2[8];
#pragma unroll
            for (int a = 0; a < 4; a++) ar2[a] = *(const u64*)&As[k][2 * lx + 32 * a];
#pragma unroll
            for (int c = 0; c < 8; c++) br2[c] = dup2(Bs[k][ly + 16 * c]);
#pragma unroll
            for (int a = 0; a < 4; a++)
#pragma unroll
                for (int c = 0; c < 8; c++) acc2[a][c] = ffma2(ar2[a], br2[c], acc2[a][c]);
        }
        __syncthreads();
    }
    int chunkbase = (b * NCHUNK + (n0 >> 8)) * COUT;
#pragma unroll
    for (int c = 0; c < 8; c++) {
        int o = o0 + ly + 16 * c;
        float bias = g_b3[o];
        float sev = g_se[chunkbase + o];
#pragma unroll
        for (int a = 0; a < 4; a++) {
            int n = n0 + 2 * lx + 32 * a;
            F2U cv; cv.u = acc2[a][c];
            float v0 = cv.f.x + bias;
            float v1 = cv.f.y + bias;
            v0 = fmaf(g_outpre[((size_t)b * Np + n) * COUT + o], sev, v0);
            v1 = fmaf(g_outpre[((size_t)b * Np + n + 1) * COUT + o], sev, v1);
            *(float2*)&out[((size_t)b * COUT + o) * Np + n] = make_float2(v0, v1);
        }
    }
}

// ---------------- launch ----------------
extern "C" void kernel_launch(void* const* d_in, const int* in_sizes, int n_in,
                              void* d_out, int out_size) {
    const float* x      = (const float*)d_in[0];
    const float* W_edge = (const float*)d_in[1];
    const float* bn1_g  = (const float*)d_in[2];
    const float* bn1_b  = (const float*)d_in[3];
    const float* bn1_m  = (const float*)d_in[4];
    const float* bn1_v  = (const float*)d_in[5];
    const float* w_att  = (const float*)d_in[6];
    const float* W_fuse = (const float*)d_in[7];
    const float* bn2_g  = (const float*)d_in[8];
    const float* bn2_b  = (const float*)d_in[9];
    const float* bn2_m  = (const float*)d_in[10];
    const float* bn2_v  = (const float*)d_in[11];
    const float* fc1_w  = (const float*)d_in[12];
    const float* fc1_b  = (const float*)d_in[13];
    const float* fc2_w  = (const float*)d_in[14];
    const float* fc2_b  = (const float*)d_in[15];
    const float* W_res  = (const float*)d_in[16];
    const float* bn3_g  = (const float*)d_in[17];
    const float* bn3_b  = (const float*)d_in[18];
    const float* bn3_m  = (const float*)d_in[19];
    const float* bn3_v  = (const float*)d_in[20];
    float* out = (float*)d_out;

    static const int d2_smem = 128 * TSTRIDE * (int)sizeof(float);  // 67584
    cudaFuncSetAttribute(d2_kernel, cudaFuncAttributeMaxDynamicSharedMemorySize, d2_smem);

    prep_kernel<<<64, 256>>>(W_edge, bn1_g, bn1_b, bn1_m, bn1_v,
                             W_fuse, bn2_g, bn2_b, bn2_m, bn2_v,
                             W_res, bn3_g, bn3_b, bn3_m, bn3_v);
    sq_kernel<<<dim3(Np / 256, Bn), 256>>>(x);
    cvt_kernel<<<dim3(Np / 32, CIN / 32, Bn), dim3(32, 8)>>>(x);
    d2_kernel<<<dim3(NT * (NT + 1) / 2, Bn), 256, d2_smem>>>();
    topk_kernel<<<dim3(Np / 8, Bn), 256>>>();
    ac_gemm<<<dim3(Np / 128, Bn, 2), 256>>>(x);
    attn_agg_kernel<<<dim3(Np, Bn), 128>>>(w_att);
    fuse_gemm<<<dim3(Np / 128, COUT / 128, Bn), 256>>>();
    se_sum_kernel<<<dim3(NCHUNK, Bn, 8), 256>>>();
    se_mlp_kernel<<<dim3(NCHUNK, Bn), 256>>>(fc1_w, fc1_b, fc2_w, fc2_b);
    final_kernel<<<dim3(Np / 128, COUT / 128, Bn), 256>>>(x, out);
}

// round 17
// speedup vs baseline: 1.2441x; 1.0233x over previous
#include <cuda_runtime.h>
#include <cuda_fp16.h>
#include <math.h>
#include <stdint.h>

#define Bn 4
#define CIN 128
#define Np 4096
#define Hd 128
#define COUT 256
#define Kn 16
#define SEH 64
#define NCHUNK 16
#define EPSB 1e-5f
#define NT 32   // 4096/128 tiles
#define TSTRIDE 132
#define WCAP 256
#define PSTR 24          // halves per point-row in smem planes
#define PLANE 6144       // bytes per plane (128 * PSTR * 2)
#define BUFB  24576      // bytes per buffer (4 planes)

typedef unsigned long long u64;

// ---------------- scratch (static __device__, no allocations) ----------------
__device__ float g_sq[Bn * Np];
__device__ float g_d2[(size_t)Bn * Np * Np];        // 256 MiB
__device__ float g_rmin[(size_t)Bn * Np * NT];      // per-(row, tile) minima
__device__ int   g_idx[Bn * Np * Kn];
__device__ __half g_xh[(size_t)Bn * Np * CIN];      // x hi, [b][n][k] point-major
__device__ __half g_xl[(size_t)Bn * Np * CIN];      // x lo
__device__ float g_W1T[CIN * Hd];                   // [c][h]
__device__ float g_WCT[CIN * Hd];                   // [c][h]
__device__ float g_beff[Hd];
__device__ float g_WfuseT[Hd * COUT];               // [h][o]
__device__ float g_b2[COUT];
__device__ float g_WresT[CIN * COUT];               // [c][o]
__device__ float g_b3[COUT];
__device__ float g_A[(size_t)Bn * Np * Hd];
__device__ float g_C[(size_t)Bn * Np * Hd];
__device__ float g_agg[(size_t)Bn * Np * Hd];
__device__ float g_outpre[(size_t)Bn * Np * COUT];
__device__ float g_separt[Bn * NCHUNK * 8 * COUT];
__device__ float g_se[Bn * NCHUNK * COUT];

__device__ __forceinline__ u64 ffma2(u64 a, u64 b, u64 c) {
    u64 d;
    asm("fma.rn.f32x2 %0, %1, %2, %3;" : "=l"(d) : "l"(a), "l"(b), "l"(c));
    return d;
}
union F2U { u64 u; float2 f; };

__device__ __forceinline__ u64 dup2(float v) {
    u64 r;
    asm("mov.b64 %0, {%1, %1};" : "=l"(r) : "f"(v));
    return r;
}

__device__ __forceinline__ u64 mk_key(float f, unsigned idx) {
    unsigned u = __float_as_uint(f);
    unsigned ord = (f < 0.f) ? ~u : (u | 0x80000000u);
    return ((u64)ord << 32) | idx;
}

__device__ __forceinline__ unsigned smem_u32(const void* p) {
    unsigned a;
    asm("{ .reg .u64 t; cvta.to.shared.u64 t, %1; cvt.u32.u64 %0, t; }"
        : "=r"(a) : "l"(p));
    return a;
}

__device__ __forceinline__ void cpa16(unsigned dst, const void* src) {
    asm volatile("cp.async.ca.shared.global [%0], [%1], 16;"
                 :: "r"(dst), "l"(src) : "memory");
}

__device__ __forceinline__ void mma_f16(float* d, const unsigned* a,
                                        unsigned b0, unsigned b1) {
    asm volatile(
        "mma.sync.aligned.m16n8k16.row.col.f32.f16.f16.f32 "
        "{%0,%1,%2,%3}, {%4,%5,%6,%7}, {%8,%9}, {%0,%1,%2,%3};"
        : "+f"(d[0]), "+f"(d[1]), "+f"(d[2]), "+f"(d[3])
        : "r"(a[0]), "r"(a[1]), "r"(a[2]), "r"(a[3]), "r"(b0), "r"(b1));
}

// ---------------- prep: fold all BN into weights ----------------
__global__ void prep_kernel(const float* __restrict__ W_edge,
                            const float* __restrict__ g1, const float* __restrict__ b1,
                            const float* __restrict__ m1, const float* __restrict__ v1,
                            const float* __restrict__ W_fuse,
                            const float* __restrict__ g2, const float* __restrict__ b2,
                            const float* __restrict__ m2, const float* __restrict__ v2,
                            const float* __restrict__ W_res,
                            const float* __restrict__ g3, const float* __restrict__ b3,
                            const float* __restrict__ m3, const float* __restrict__ v3) {
    int i = blockIdx.x * blockDim.x + threadIdx.x;
    int stride = gridDim.x * blockDim.x;
    for (int t = i; t < CIN * Hd; t += stride) {
        int h = t % Hd, c = t / Hd;
        float s = g1[h] * rsqrtf(v1[h] + EPSB);
        float w1 = W_edge[h * (2 * CIN) + c];
        float w2 = W_edge[h * (2 * CIN) + CIN + c];
        g_W1T[t] = w1 * s;
        g_WCT[t] = (w2 - w1) * s;
    }
    for (int h = i; h < Hd; h += stride) {
        float s = g1[h] * rsqrtf(v1[h] + EPSB);
        g_beff[h] = b1[h] - m1[h] * s;
    }
    for (int t = i; t < Hd * COUT; t += stride) {
        int o = t % COUT, h = t / COUT;
        float s = g2[o] * rsqrtf(v2[o] + EPSB);
        g_WfuseT[t] = W_fuse[o * Hd + h] * s;
    }
    for (int o = i; o < COUT; o += stride) {
        float s2 = g2[o] * rsqrtf(v2[o] + EPSB);
        g_b2[o] = b2[o] - m2[o] * s2;
        float s3 = g3[o] * rsqrtf(v3[o] + EPSB);
        g_b3[o] = b3[o] - m3[o] * s3;
    }
    for (int t = i; t < CIN * COUT; t += stride) {
        int o = t % COUT, c = t / COUT;
        float s3 = g3[o] * rsqrtf(v3[o] + EPSB);
        g_WresT[t] = W_res[o * CIN + c] * s3;
    }
}

// ---------------- squared norms ----------------
__global__ void sq_kernel(const float* __restrict__ x) {
    int b = blockIdx.y;
    int n = blockIdx.x * 256 + threadIdx.x;
    const float* xb = x + (size_t)b * CIN * Np;
    float s = 0.f;
    for (int c = 0; c < CIN; c++) {
        float v = xb[(size_t)c * Np + n];
        s = fmaf(v, v, s);
    }
    g_sq[b * Np + n] = s;
}

// ---------------- fp16 hi/lo split + transpose to [n][k] ----------------
__global__ void cvt_kernel(const float* __restrict__ x) {
    int b = blockIdx.z;
    int n0 = blockIdx.x * 32, k0 = blockIdx.y * 32;
    int tx = threadIdx.x, ty = threadIdx.y;   // (32, 8)
    const float* xb = x + (size_t)b * CIN * Np;
    __shared__ __half th[32][34], tl[32][34];   // [n][k] tile
    for (int r = ty; r < 32; r += 8) {
        float v = xb[(size_t)(k0 + r) * Np + n0 + tx];
        __half h = __float2half(v);
        __half l = __float2half(v - __half2float(h));
        th[tx][r] = h;
        tl[tx][r] = l;
    }
    __syncthreads();
    for (int r = ty; r < 32; r += 8) {
        g_xh[((size_t)b * Np + n0 + r) * CIN + k0 + tx] = th[r][tx];
        g_xl[((size_t)b * Np + n0 + r) * CIN + k0 + tx] = tl[r][tx];
    }
}

// ---------------- symmetric d2 via fp16-split m16n8k16 HMMA -------------------
// dot = hi*hi' + hi*lo' + lo*hi'; dropped lo*lo' <= 2^-22 rel. d2 only selects
// neighbor indices (values unused downstream) -> selection provably unchanged.
// cp.async double-buffered k-chunk staging hides gmem latency behind MMAs.
extern __shared__ __align__(16) char s_raw[];

__global__ __launch_bounds__(256, 2) void d2_kernel() {
    int b = blockIdx.y;
    int ti = 0, rem = blockIdx.x;
    while (rem >= NT - ti) { rem -= NT - ti; ti++; }
    int tj = ti + rem;
    int i0 = ti * 128, j0 = tj * 128;

    char* smc = s_raw;                        // 2 buffers x 4 planes x 6KB
    float* s_tile = (float*)s_raw;            // epilogue overlay (67.6KB)
    __shared__ float s_sqi[128], s_sqj[128], colmin[128];

    int tid = threadIdx.x;
    int lane = tid & 31, w = tid >> 5;
    if (tid < 128) s_sqi[tid] = g_sq[b * Np + i0 + tid];
    else           s_sqj[tid - 128] = g_sq[b * Np + j0 + tid - 128];

    float acc[2][8][4];
#pragma unroll
    for (int s = 0; s < 2; s++)
#pragma unroll
        for (int j = 0; j < 8; j++)
#pragma unroll
            for (int q = 0; q < 4; q++) acc[s][j][q] = 0.f;

    int m0w = (w >> 1) * 32;
    int n0w = (w & 1) * 64;
    int g = lane >> 2, t = lane & 3;
    int lp = tid >> 1, lseg = (tid & 1) * 8;   // staging: point, 8-half segment

    const __half* xhA = g_xh + ((size_t)b * Np + i0 + lp) * CIN + lseg;
    const __half* xlA = g_xl + ((size_t)b * Np + i0 + lp) * CIN + lseg;
    const __half* xhB = g_xh + ((size_t)b * Np + j0 + lp) * CIN + lseg;
    const __half* xlB = g_xl + ((size_t)b * Np + j0 + lp) * CIN + lseg;
    unsigned sb = smem_u32(smc) + (unsigned)(lp * PSTR + lseg) * 2;

    // stage chunk 0 into buffer 0
    {
        cpa16(sb,             xhA);
        cpa16(sb + PLANE,     xlA);
        cpa16(sb + 2 * PLANE, xhB);
        cpa16(sb + 3 * PLANE, xlB);
        asm volatile("cp.async.commit_group;" ::: "memory");
        asm volatile("cp.async.wait_group 0;" ::: "memory");
    }
    __syncthreads();

    for (int c = 0; c < 8; c++) {
        int buf = c & 1;
        if (c < 7) {
            unsigned dst = sb + (buf ^ 1) * BUFB;
            int kofs = (c + 1) * 16;
            cpa16(dst,             xhA + kofs);
            cpa16(dst + PLANE,     xlA + kofs);
            cpa16(dst + 2 * PLANE, xhB + kofs);
            cpa16(dst + 3 * PLANE, xlB + kofs);
            asm volatile("cp.async.commit_group;" ::: "memory");
        }
        const __half* sAh = (const __half*)(smc + buf * BUFB);
        const __half* sAl = (const __half*)(smc + buf * BUFB + PLANE);
        const __half* sBh = (const __half*)(smc + buf * BUFB + 2 * PLANE);
        const __half* sBl = (const __half*)(smc + buf * BUFB + 3 * PLANE);

        unsigned ah[2][4], al[2][4];
#pragma unroll
        for (int s = 0; s < 2; s++) {
            int base = (m0w + 16 * s + g) * PSTR;
            ah[s][0] = *(const unsigned*)&sAh[base + 2 * t];
            ah[s][1] = *(const unsigned*)&sAh[base + 8 * PSTR + 2 * t];
            ah[s][2] = *(const unsigned*)&sAh[base + 2 * t + 8];
            ah[s][3] = *(const unsigned*)&sAh[base + 8 * PSTR + 2 * t + 8];
            al[s][0] = *(const unsigned*)&sAl[base + 2 * t];
            al[s][1] = *(const unsigned*)&sAl[base + 8 * PSTR + 2 * t];
            al[s][2] = *(const unsigned*)&sAl[base + 2 * t + 8];
            al[s][3] = *(const unsigned*)&sAl[base + 8 * PSTR + 2 * t + 8];
        }
#pragma unroll
        for (int j = 0; j < 8; j++) {
            int bbase = (n0w + 8 * j + g) * PSTR;
            unsigned bh0 = *(const unsigned*)&sBh[bbase + 2 * t];
            unsigned bh1 = *(const unsigned*)&sBh[bbase + 2 * t + 8];
            unsigned bl0 = *(const unsigned*)&sBl[bbase + 2 * t];
            unsigned bl1 = *(const unsigned*)&sBl[bbase + 2 * t + 8];
#pragma unroll
            for (int s = 0; s < 2; s++) {
                mma_f16(acc[s][j], ah[s], bh0, bh1);
                mma_f16(acc[s][j], ah[s], bl0, bl1);
                mma_f16(acc[s][j], al[s], bh0, bh1);
            }
        }
        if (c < 7) asm volatile("cp.async.wait_group 0;" ::: "memory");
        __syncthreads();
    }

    // stage d2 = sq_i + sq_j - 2*dot into s_tile
    int g_ = lane >> 2, t_ = lane & 3;
#pragma unroll
    for (int s = 0; s < 2; s++) {
        int r = m0w + 16 * s + g_;
        float sq0 = s_sqi[r], sq1 = s_sqi[r + 8];
#pragma unroll
        for (int j = 0; j < 8; j++) {
            int c = n0w + 8 * j + 2 * t_;
            float sj0 = s_sqj[c], sj1 = s_sqj[c + 1];
            *(float2*)&s_tile[r * TSTRIDE + c] =
                make_float2(sq0 + sj0 - 2.f * acc[s][j][0],
                            sq0 + sj1 - 2.f * acc[s][j][1]);
            *(float2*)&s_tile[(r + 8) * TSTRIDE + c] =
                make_float2(sq1 + sj0 - 2.f * acc[s][j][2],
                            sq1 + sj1 - 2.f * acc[s][j][3]);
        }
    }
    __syncthreads();

    float* d2b = g_d2 + (size_t)b * Np * Np;
    // direct store (coalesced float4) + fused row minima
    {
        int r = tid >> 1, h = tid & 1;
        const float4* src = (const float4*)(s_tile + r * TSTRIDE + h * 64);
        float4* dst = (float4*)(d2b + (size_t)(i0 + r) * Np + j0 + h * 64);
        float rm = INFINITY;
#pragma unroll
        for (int q = 0; q < 16; q++) {
            float4 v = src[q];
            dst[q] = v;
            rm = fminf(rm, fminf(fminf(v.x, v.y), fminf(v.z, v.w)));
        }
        float o = __shfl_xor_sync(0xffffffffu, rm, 1);
        rm = fminf(rm, o);
        if (h == 0) g_rmin[((size_t)(b * Np + i0 + r)) * NT + tj] = rm;
    }
    if (ti != tj) {
        // transposed store (coalesced over il)
        for (int idx = tid; idx < 128 * 128; idx += 256) {
            int jl = idx >> 7, il = idx & 127;
            d2b[(size_t)(j0 + jl) * Np + i0 + il] = s_tile[il * TSTRIDE + jl];
        }
        // column minima -> row minima of the mirrored rows (2 threads/col)
        {
            int col = tid & 127, half = tid >> 7;
            float cm = INFINITY;
            int il0 = half * 64;
            for (int il = il0; il < il0 + 64; il++)
                cm = fminf(cm, s_tile[il * TSTRIDE + col]);
            if (half == 0) colmin[col] = cm;
            __syncthreads();
            if (half == 1)
                g_rmin[((size_t)(b * Np + j0 + col)) * NT + ti] = fminf(cm, colmin[col]);
        }
    }
}

// ---------------- top-16: warp-per-row, tile-min threshold + tile skipping ----
__global__ __launch_bounds__(256, 8) void topk_kernel() {
    int tid = threadIdx.x;
    int lane = tid & 31, w = tid >> 5;
    int b = blockIdx.y;
    int n = blockIdx.x * 8 + w;
    const float* row = g_d2 + ((size_t)b * Np + n) * Np;

    __shared__ u64 wcand[8][WCAP];   // 16 KB, per-warp segments

    float rm = g_rmin[((size_t)(b * Np + n)) * NT + lane];
    {
        float v = rm;
#pragma unroll
        for (int k = 2; k <= 32; k <<= 1) {
#pragma unroll
            for (int j = k >> 1; j > 0; j >>= 1) {
                float o = __shfl_xor_sync(0xffffffffu, v, j);
                bool dirDesc = (lane & k) != 0;
                bool lower = (lane & j) == 0;
                bool takeMin = (lower != dirDesc);
                v = takeMin ? fminf(v, o) : fmaxf(v, o);
            }
        }
        float Tf_ = __shfl_sync(0xffffffffu, v, 15);
        unsigned tmask = __ballot_sync(0xffffffffu, rm <= Tf_);
        int cnt = 0;
        bool over = false;
        unsigned m = tmask;
        while (m) {
            int t = __ffs(m) - 1;
            m &= m - 1;
            float4 vv = *(const float4*)(row + t * 128 + lane * 4);
            float fv[4] = {vv.x, vv.y, vv.z, vv.w};
#pragma unroll
            for (int q = 0; q < 4; q++) {
                bool p = fv[q] <= Tf_;
                unsigned bm = __ballot_sync(0xffffffffu, p);
                if (p) {
                    int pos = cnt + __popc(bm & ((1u << lane) - 1u));
                    if (pos < WCAP) wcand[w][pos] = mk_key(fv[q], t * 128 + lane * 4 + q);
                    else over = true;
                }
                cnt += __popc(bm);
            }
        }
        over = __any_sync(0xffffffffu, over) || (cnt > WCAP);
        __syncwarp();

        int* outp = g_idx + ((b * Np + n) * Kn);
        if (!over) {
            for (int it = 0; it < Kn; it++) {
                u64 best = ~0ull; int bslot = -1;
                for (int s = lane; s < cnt; s += 32) {
                    u64 kk = wcand[w][s];
                    if (kk < best) { best = kk; bslot = s; }
                }
                u64 k = best;
#pragma unroll
                for (int off = 16; off; off >>= 1) {
                    u64 o = __shfl_xor_sync(0xffffffffu, k, off);
                    if (o < k) k = o;
                }
                if (lane == 0) outp[it] = (int)(unsigned)(k & 0xffffffffull);
                if (best == k && bslot >= 0) wcand[w][bslot] = ~0ull;
                __syncwarp();
            }
        } else {
            u64 last = 0;
            for (int it = 0; it < Kn; it++) {
                u64 best = ~0ull;
                for (int s = lane; s < Np; s += 32) {
                    u64 kk = mk_key(row[s], s);
                    if (kk > last && kk < best) best = kk;
                }
                u64 k = best;
#pragma unroll
                for (int off = 16; off; off >>= 1) {
                    u64 o = __shfl_xor_sync(0xffffffffu, k, off);
                    if (o < k) k = o;
                }
                if (lane == 0) outp[it] = (int)(unsigned)(k & 0xffffffffull);
                last = k;
            }
        }
    }
}

// ---------------- A/C projection GEMMs (FFMA2, non-dup A) ----------------
__global__ __launch_bounds__(256, 2) void ac_gemm(const float* __restrict__ x) {
    int b = blockIdx.y;
    int n0 = blockIdx.x * 128;
    int which = blockIdx.z;
    const float* WT = which ? g_WCT : g_W1T;  // [c][h], h contiguous
    const float* xb = x + (size_t)b * CIN * Np;
    __shared__ __align__(16) float As[8][132];
    __shared__ __align__(16) float Bs[8][128];
    u64 acc2[8][4];
#pragma unroll
    for (int a = 0; a < 8; a++)
#pragma unroll
        for (int c = 0; c < 4; c++) acc2[a][c] = 0ull;
    int tid = threadIdx.x;
    int lx = tid & 15, ly = tid >> 4;
    int loadc = tid >> 5, loadi = (tid & 31) * 4;
    for (int c0 = 0; c0 < CIN; c0 += 8) {
        *(float4*)&As[loadc][loadi] = *(const float4*)(xb + (size_t)(c0 + loadc) * Np + n0 + loadi);
        *(float4*)&Bs[loadc][loadi] = *(const float4*)(WT + (size_t)(c0 + loadc) * Hd + loadi);
        __syncthreads();
#pragma unroll
        for (int k = 0; k < 8; k++) {
            u64 ar2[8], br2[4];
#pragma unroll
            for (int a = 0; a < 8; a++) ar2[a] = dup2(As[k][ly + 16 * a]);
#pragma unroll
            for (int c = 0; c < 4; c++) br2[c] = *(const u64*)&Bs[k][2 * lx + 32 * c];
#pragma unroll
            for (int a = 0; a < 8; a++)
#pragma unroll
                for (int c = 0; c < 4; c++) acc2[a][c] = ffma2(ar2[a], br2[c], acc2[a][c]);
        }
        __syncthreads();
    }
    float* outb = which ? g_C : g_A;
#pragma unroll
    for (int a = 0; a < 8; a++) {
        int n = n0 + ly + 16 * a;
#pragma unroll
        for (int c = 0; c < 4; c++) {
            int h = 2 * lx + 32 * c;
            F2U cv; cv.u = acc2[a][c];
            float v0 = cv.f.x, v1 = cv.f.y;
            if (which) {
                float2 be = *(const float2*)&g_beff[h];
                v0 += be.x; v1 += be.y;
            }
            *(float2*)&outb[((size_t)b * Np + n) * Hd + h] = make_float2(v0, v1);
        }
    }
}

// ---------------- attention + aggregate (per query), write g_agg ----------------
__global__ __launch_bounds__(128) void attn_agg_kernel(const float* __restrict__ w_att) {
    int b = blockIdx.y, n = blockIdx.x;
    int tid = threadIdx.x;  // == h channel, 128
    __shared__ float shp[4][Kn];
    __shared__ float tk[Kn];
    const int* id = g_idx + ((b * Np + n) * Kn);
    const float* Ab = g_A + (size_t)b * Np * Hd;
    float Cc = g_C[((size_t)b * Np + n) * Hd + tid];
    float hk[Kn];
#pragma unroll
    for (int k = 0; k < Kn; k++) {
        int j = id[k];
        hk[k] = fmaxf(Ab[(size_t)j * Hd + tid] + Cc, 0.f);
    }
    float wa = w_att[tid];
    int lane = tid & 31, w = tid >> 5;
#pragma unroll
    for (int k = 0; k < Kn; k++) {
        float p = hk[k] * wa;
#pragma unroll
        for (int off = 16; off > 0; off >>= 1) p += __shfl_down_sync(0xffffffffu, p, off);
        if (lane == 0) shp[w][k] = p;
    }
    __syncthreads();
    if (tid < Kn) tk[tid] = shp[0][tid] + shp[1][tid] + shp[2][tid] + shp[3][tid];
    __syncthreads();
    float mx = -INFINITY;
#pragma unroll
    for (int k = 0; k < Kn; k++) mx = fmaxf(mx, tk[k]);
    float e[Kn]; float ssum = 0.f;
#pragma unroll
    for (int k = 0; k < Kn; k++) { e[k] = __expf(tk[k] - mx); ssum += e[k]; }
    float inv = 1.f / ssum;
    float agg = 0.f;
#pragma unroll
    for (int k = 0; k < Kn; k++) agg = fmaf(e[k], hk[k], agg);
    g_agg[((size_t)b * Np + n) * Hd + tid] = agg * inv;
}

// ---------------- fuse GEMM: relu(agg @ WfuseT + b2) -> g_outpre ----------------
__global__ __launch_bounds__(256, 2) void fuse_gemm() {
    int b = blockIdx.z;
    int n0 = blockIdx.x * 128;
    int o0 = blockIdx.y * 128;
    __shared__ __align__(16) float As[8][132];    // [h][n] (transposed in)
    __shared__ __align__(16) float Bs[8][128];    // [h][o]
    u64 acc2[8][4];   // [a: n][c: o-pairs]
    int tid = threadIdx.x;
    int lx = tid & 15, ly = tid >> 4;
#pragma unroll
    for (int c = 0; c < 4; c++) {
        u64 bias = *(const u64*)&g_b2[o0 + 2 * lx + 32 * c];
#pragma unroll
        for (int a = 0; a < 8; a++) acc2[a][c] = bias;
    }
    int arow = tid >> 1, acol = tid & 1;
    int loadc = tid >> 5, loadi = (tid & 31) * 4;
    for (int c0 = 0; c0 < Hd; c0 += 8) {
        float4 va = *(const float4*)(g_agg + ((size_t)b * Np + n0 + arow) * Hd + c0 + 4 * acol);
        As[4 * acol + 0][arow] = va.x;
        As[4 * acol + 1][arow] = va.y;
        As[4 * acol + 2][arow] = va.z;
        As[4 * acol + 3][arow] = va.w;
        *(float4*)&Bs[loadc][loadi] = *(const float4*)(g_WfuseT + (size_t)(c0 + loadc) * COUT + o0 + loadi);
        __syncthreads();
#pragma unroll
        for (int k = 0; k < 8; k++) {
            u64 ar2[8], br2[4];
#pragma unroll
            for (int a = 0; a < 8; a++) ar2[a] = dup2(As[k][ly + 16 * a]);
#pragma unroll
            for (int c = 0; c < 4; c++) br2[c] = *(const u64*)&Bs[k][2 * lx + 32 * c];
#pragma unroll
            for (int a = 0; a < 8; a++)
#pragma unroll
                for (int c = 0; c < 4; c++) acc2[a][c] = ffma2(ar2[a], br2[c], acc2[a][c]);
        }
        __syncthreads();
    }
#pragma unroll
    for (int a = 0; a < 8; a++) {
        int n = n0 + ly + 16 * a;
#pragma unroll
        for (int c = 0; c < 4; c++) {
            int o = o0 + 2 * lx + 32 * c;
            F2U cv; cv.u = acc2[a][c];
            *(float2*)&g_outpre[((size_t)b * Np + n) * COUT + o] =
                make_float2(fmaxf(cv.f.x, 0.f), fmaxf(cv.f.y, 0.f));
        }
    }
}

// ---------------- SE stage 1: partial sums (512 blocks) ----------------
__global__ __launch_bounds__(256) void se_sum_kernel() {
    int b = blockIdx.y, ch = blockIdx.x, z = blockIdx.z;
    int tid = threadIdx.x;
    const float* op = g_outpre + ((size_t)b * Np + (size_t)ch * 256 + (size_t)z * 32) * COUT;
    float s = 0.f;
#pragma unroll 8
    for (int q = 0; q < 32; q++) s += op[(size_t)q * COUT + tid];
    g_separt[(((b * NCHUNK) + ch) * 8 + z) * COUT + tid] = s;
}

// ---------------- SE stage 2: combine + MLP ----------------
__global__ __launch_bounds__(256) void se_mlp_kernel(const float* __restrict__ fc1_w,
                                                     const float* __restrict__ fc1_b,
                                                     const float* __restrict__ fc2_w,
                                                     const float* __restrict__ fc2_b) {
    int b = blockIdx.y, ch = blockIdx.x;
    int tid = threadIdx.x;
    float s = 0.f;
#pragma unroll
    for (int z = 0; z < 8; z++)
        s += g_separt[(((b * NCHUNK) + ch) * 8 + z) * COUT + tid];
    __shared__ float mean[COUT];
    __shared__ float u[SEH];
    mean[tid] = s * (1.f / 256.f);
    __syncthreads();
    if (tid < SEH) {
        float acc = fc1_b[tid];
        for (int c = 0; c < COUT; c++) acc = fmaf(mean[c], fc1_w[tid * COUT + c], acc);
        u[tid] = fmaxf(acc, 0.f);
    }
    __syncthreads();
    float acc = fc2_b[tid];
#pragma unroll
    for (int j = 0; j < SEH; j++) acc = fmaf(u[j], fc2_w[tid * SEH + j], acc);
    g_se[(b * NCHUNK + ch) * COUT + tid] = 1.f / (1.f + __expf(-acc));
}

// ---------------- residual GEMM (FFMA2, non-dup B) + SE-scale + combine --------
__global__ __launch_bounds__(256, 2) void final_kernel(const float* __restrict__ x,
                                                       float* __restrict__ out) {
    int b = blockIdx.z;
    int n0 = blockIdx.x * 128;
    int o0 = blockIdx.y * 128;
    const float* xb = x + (size_t)b * CIN * Np;
    __shared__ __align__(16) float As[8][128];    // n-tile (pairs native)
    __shared__ __align__(16) float Bs[8][132];    // o-tile plain
    u64 acc2[4][8];  // [n-pair][o]
#pragma unroll
    for (int a = 0; a < 4; a++)
#pragma unroll
        for (int c = 0; c < 8; c++) acc2[a][c] = 0ull;
    int tid = threadIdx.x;
    int lx = tid & 15, ly = tid >> 4;  // lx -> n pairs, ly -> o
    int loadc = tid >> 5, loadi = (tid & 31) * 4;
    for (int c0 = 0; c0 < CIN; c0 += 8) {
        *(float4*)&As[loadc][loadi] = *(const float4*)(xb + (size_t)(c0 + loadc) * Np + n0 + loadi);
        *(float4*)&Bs[loadc][loadi] = *(const float4*)(g_WresT + (size_t)(c0 + loadc) * COUT + o0 + loadi);
        __syncthreads();
#pragma unroll
        for (int k = 0; k < 8; k++) {
            u64 ar2[4], br2[8];
#pragma unroll
            for (int a = 0; a < 4; a++) ar2[a] = *(const u64*)&As[k][2 * lx + 32 * a];
#pragma unroll
            for (int c = 0; c < 8; c++) br2[c] = dup2(Bs[k][ly + 16 * c]);
#pragma unroll
            for (int a = 0; a < 4; a++)
#pragma unroll
                for (int c = 0; c < 8; c++) acc2[a][c] = ffma2(ar2[a], br2[c], acc2[a][c]);
        }
        __syncthreads();
    }
    int chunkbase = (b * NCHUNK + (n0 >> 8)) * COUT;
#pragma unroll
    for (int c = 0; c < 8; c++) {
        int o = o0 + ly + 16 * c;
        float bias = g_b3[o];
        float sev = g_se[chunkbase + o];
#pragma unroll
        for (int a = 0; a < 4; a++) {
            int n = n0 + 2 * lx + 32 * a;
            F2U cv; cv.u = acc2[a][c];
            float v0 = cv.f.x + bias;
            float v1 = cv.f.y + bias;
            v0 = fmaf(g_outpre[((size_t)b * Np + n) * COUT + o], sev, v0);
            v1 = fmaf(g_outpre[((size_t)b * Np + n + 1) * COUT + o], sev, v1);
            *(float2*)&out[((size_t)b * COUT + o) * Np + n] = make_float2(v0, v1);
        }
    }
}

// ---------------- launch ----------------
extern "C" void kernel_launch(void* const* d_in, const int* in_sizes, int n_in,
                              void* d_out, int out_size) {
    const float* x      = (const float*)d_in[0];
    const float* W_edge = (const float*)d_in[1];
    const float* bn1_g  = (const float*)d_in[2];
    const float* bn1_b  = (const float*)d_in[3];
    const float* bn1_m  = (const float*)d_in[4];
    const float* bn1_v  = (const float*)d_in[5];
    const float* w_att  = (const float*)d_in[6];
    const float* W_fuse = (const float*)d_in[7];
    const float* bn2_g  = (const float*)d_in[8];
    const float* bn2_b  = (const float*)d_in[9];
    const float* bn2_m  = (const float*)d_in[10];
    const float* bn2_v  = (const float*)d_in[11];
    const float* fc1_w  = (const float*)d_in[12];
    const float* fc1_b  = (const float*)d_in[13];
    const float* fc2_w  = (const float*)d_in[14];
    const float* fc2_b  = (const float*)d_in[15];
    const float* W_res  = (const float*)d_in[16];
    const float* bn3_g  = (const float*)d_in[17];
    const float* bn3_b  = (const float*)d_in[18];
    const float* bn3_m  = (const float*)d_in[19];
    const float* bn3_v  = (const float*)d_in[20];
    float* out = (float*)d_out;

    static const int d2_smem = 128 * TSTRIDE * (int)sizeof(float);  // 67584
    cudaFuncSetAttribute(d2_kernel, cudaFuncAttributeMaxDynamicSharedMemorySize, d2_smem);

    prep_kernel<<<64, 256>>>(W_edge, bn1_g, bn1_b, bn1_m, bn1_v,
                             W_fuse, bn2_g, bn2_b, bn2_m, bn2_v,
                             W_res, bn3_g, bn3_b, bn3_m, bn3_v);
    sq_kernel<<<dim3(Np / 256, Bn), 256>>>(x);
    cvt_kernel<<<dim3(Np / 32, CIN / 32, Bn), dim3(32, 8)>>>(x);
    d2_kernel<<<dim3(NT * (NT + 1) / 2, Bn), 256, d2_smem>>>();
    topk_kernel<<<dim3(Np / 8, Bn), 256>>>();
    ac_gemm<<<dim3(Np / 128, Bn, 2), 256>>>(x);
    attn_agg_kernel<<<dim3(Np, Bn), 128>>>(w_att);
    fuse_gemm<<<dim3(Np / 128, COUT / 128, Bn), 256>>>();
    se_sum_kernel<<<dim3(NCHUNK, Bn, 8), 256>>>();
    se_mlp_kernel<<<dim3(NCHUNK, Bn), 256>>>(fc1_w, fc1_b, fc2_w, fc2_b);
    final_kernel<<<dim3(Np / 128, COUT / 128, Bn), 256>>>(x, out);
}